// round 12
// baseline (speedup 1.0000x reference)
#include <cuda_runtime.h>
#include <cstdint>
#include <math.h>

#define NB 32
#define TVn 3200
#define BN_INV 0.9999950000374997f

// ---------------- scratch (__device__ globals; allocation-free) ----------------
__device__ float g_wp  [327680];
__device__ float g_xT  [(size_t)NB*TVn*128];
__device__ float g_qkT [(size_t)NB*TVn*192];
__device__ float g_atts[(size_t)NB*3*128*704];    // [n][s][t][25][28] v-padded
__device__ float g_yT  [(size_t)NB*TVn*384];
__device__ float g_s1T [(size_t)NB*TVn*128];
__device__ float g_soT [(size_t)NB*TVn*128];
__device__ float g_sbar[(size_t)NB*128*128];
__device__ float g_qtm [(size_t)NB*128*256];
__device__ float g_att [(size_t)NB*4*128*128];
__device__ float g_tmaj[(size_t)NB*25*128*128];
__device__ float g_zT  [(size_t)NB*TVn*512];
__device__ float g_toT [(size_t)NB*TVn*128];
__device__ float g_tnc [(size_t)NB*128*TVn];

#define OFF_WINS  0
#define OFF_WOUTS 32768
#define OFF_WFFS  81920
#define OFF_WINT  98304
#define OFF_WOUTT 131072
#define OFF_WFFT  196608
#define OFF_WTCN  212992
#define W_TOTAL   327680

// smem: plain row-major tiles, row stride 36 floats (144B) -> conflict-free ldmatrix
#define RS     36
#define BOFF_F 4608
#define STG_F  9216
#define NSTAGE 3
#define SMEMSZ (STG_F * NSTAGE * 4) // 110592 bytes
#define PGRID  296                  // persistent grid (2 CTAs/SM * 148)

// ---------------- helpers ----------------
__device__ __forceinline__ uint32_t smem_u32(const void* p){
    uint32_t a;
    asm("{ .reg .u64 t; cvta.to.shared.u64 t, %1; cvt.u32.u64 %0, t; }" : "=r"(a) : "l"(p));
    return a;
}
__device__ __forceinline__ uint32_t f2tf32(float f){
    uint32_t r; asm("cvt.rna.tf32.f32 %0, %1;" : "=r"(r) : "f"(f)); return r;
}
__device__ __forceinline__ float tanh_ap(float x){
    float r; asm("tanh.approx.f32 %0, %1;" : "=f"(r) : "f"(x)); return r;
}
__device__ __forceinline__ void mma_tf32(float* d, const uint32_t* a, const uint32_t* b){
    asm volatile("mma.sync.aligned.m16n8k8.row.col.f32.tf32.tf32.f32 "
        "{%0,%1,%2,%3}, {%4,%5,%6,%7}, {%8,%9}, {%0,%1,%2,%3};"
        : "+f"(d[0]), "+f"(d[1]), "+f"(d[2]), "+f"(d[3])
        : "r"(a[0]), "r"(a[1]), "r"(a[2]), "r"(a[3]), "r"(b[0]), "r"(b[1]));
}

__device__ __forceinline__ void compute_chunk(uint32_t stage_b, int lane,
                                              int wm, int wn, float acc[4][4][4]){
    const int arow = (lane & 7) + ((lane >> 3) & 1) * 8;
    const uint32_t aoff = ((lane >> 4) & 1) * 16;
    const int brow = lane & 7;
    const uint32_t boff = ((lane >> 3) & 1) * 16;
    const uint32_t abase = stage_b + (uint32_t)((wm + arow) * RS) * 4u + aoff;
    const uint32_t bbase = stage_b + (uint32_t)(BOFF_F + (wn + brow) * RS) * 4u + boff;
    #pragma unroll
    for (int k8 = 0; k8 < 4; k8++){
        uint32_t af[4][4], bf[4][2];
        #pragma unroll
        for (int mt = 0; mt < 4; mt++){
            uint32_t ad = abase + (uint32_t)(mt * 16 * RS) * 4u + k8 * 32;
            asm volatile("ldmatrix.sync.aligned.m8n8.x4.shared.b16 {%0,%1,%2,%3}, [%4];"
                : "=r"(af[mt][0]), "=r"(af[mt][1]), "=r"(af[mt][2]), "=r"(af[mt][3])
                : "r"(ad));
        }
        #pragma unroll
        for (int nt = 0; nt < 4; nt++){
            uint32_t bd = bbase + (uint32_t)(nt * 8 * RS) * 4u + k8 * 32;
            asm volatile("ldmatrix.sync.aligned.m8n8.x2.shared.b16 {%0,%1}, [%2];"
                : "=r"(bf[nt][0]), "=r"(bf[nt][1])
                : "r"(bd));
        }
        #pragma unroll
        for (int mt = 0; mt < 4; mt++)
            #pragma unroll
            for (int nt = 0; nt < 4; nt++)
                mma_tf32(acc[mt][nt], af[mt], bf[nt]);
    }
}

// ---------------- persistent tensor-core GEMM ----------------
// Each CTA walks tiles bid, bid+grid, ...; cp.async pipeline is continuous across
// tiles (stage = global chunk mod 3). Epilogue uses the just-freed stage buffer
// in 2 half-column passes, overlapping the next tile's in-flight loads.
template<int ZMODE,int BSHIFT,int CM,bool BIAS,bool BNORM,bool RES,bool LRELU,bool PRED>
__global__ __launch_bounds__(256,2)
void mma_gemm(const float* __restrict__ A, const float* __restrict__ Bp,
              float* __restrict__ Cp,
              const float* __restrict__ bias, const float* __restrict__ gam,
              const float* __restrict__ bet, const float* __restrict__ resT,
              int Ka, int Bld, int ldc, int Mvalid, int nch, int Np,
              int ntiles, int gx, int gxy)
{
    extern __shared__ uint32_t sm[];
    const uint32_t sbw = smem_u32(sm);
    const int tid = threadIdx.x, lane = tid & 31, wid = tid >> 5;
    const int wm = (wid >> 2) * 64, wn = (wid & 3) * 32;
    const int lq = lane >> 2, klo = lane & 3;
    const int r = tid & 127, kh = (tid >> 7) * 16;

    int tile_c = blockIdx.x;
    if (tile_c >= ntiles) return;

    // ---- tile decoders ----
    // issue-side state
    int tile_i = blockIdx.x, c_i = 0, st_i = 0;
    const float *paI, *pbI; int p0I;
#define DECODE_I() { \
        int bz_ = tile_i / gxy; int r2_ = tile_i - bz_ * gxy; \
        int by_ = r2_ / gx; int bx_ = r2_ - by_ * gx; \
        int nI_, s4I_ = 0, v25I_ = 0; \
        if (ZMODE == 0) { nI_ = bz_; } \
        else { nI_ = bz_ / 100; int rr_ = bz_ % 100; s4I_ = rr_ / 25; v25I_ = rr_ % 25; } \
        p0I = (ZMODE == 0) ? bx_ * 128 : 0; \
        const float* Ab_ = (ZMODE == 0) ? A : A + (size_t)(nI_*4 + s4I_) * 16384; \
        const float* Bb_ = (ZMODE == 0) ? Bp + (size_t)nI_ * Np * Bld \
                                        : Bp + (size_t)(nI_*25 + v25I_) * 16384; \
        paI = Ab_ + (size_t)(by_ * 128 + r) * Ka + kh; \
        pbI = Bb_ + kh; }

    // compute-side state (for epilogue)
    int nC, s4C = 0, v25C = 0, m0C, p0C;
#define DECODE_C() { \
        int bz_ = tile_c / gxy; int r2_ = tile_c - bz_ * gxy; \
        int by_ = r2_ / gx; int bx_ = r2_ - by_ * gx; \
        if (ZMODE == 0) { nC = bz_; } \
        else { nC = bz_ / 100; int rr_ = bz_ % 100; s4C = rr_ / 25; v25C = rr_ % 25; } \
        m0C = by_ * 128; p0C = (ZMODE == 0) ? bx_ * 128 : 0; }

#define ISSUE_I() { \
        int k0_ = c_i * 32, k0B_, grow_; \
        if (BSHIFT){ int j_ = c_i >> 2; k0B_ = (c_i & 3) * 32; \
                     grow_ = p0I + r + (j_ - 3) * 25; } \
        else { k0B_ = k0_; grow_ = p0I + r; } \
        const bool ok_ = (!BSHIFT) || ((unsigned)grow_ < (unsigned)TVn); \
        const int bsz_ = ok_ ? 16 : 0; \
        const float* asrc_ = paI + k0_; \
        const float* bsrc_ = pbI + (size_t)(ok_ ? grow_ : 0) * Bld + k0B_; \
        const uint32_t ad_ = sbw + 4u * (st_i * STG_F + r * RS + kh); \
        const uint32_t bd_ = ad_ + 4u * BOFF_F; \
        _Pragma("unroll") \
        for (int i = 0; i < 4; i++){ \
            asm volatile("cp.async.cg.shared.global [%0], [%1], 16;" \
                         :: "r"(ad_ + 16u*i), "l"(asrc_ + i*4) : "memory"); \
            asm volatile("cp.async.cg.shared.global [%0], [%1], 16, %2;" \
                         :: "r"(bd_ + 16u*i), "l"(bsrc_ + i*4), "r"(bsz_) : "memory"); \
        } }

#define ADV_I() { if (++c_i == nch){ c_i = 0; tile_i += gridDim.x; \
                                     if (tile_i < ntiles) DECODE_I(); } \
                  if (++st_i == NSTAGE) st_i = 0; }

    DECODE_I();
    DECODE_C();

    float acc[4][4][4];
    #pragma unroll
    for (int a = 0; a < 4; a++)
        #pragma unroll
        for (int b = 0; b < 4; b++)
            #pragma unroll
            for (int c = 0; c < 4; c++) acc[a][b][c] = 0.f;

    // prologue: 2 chunks in flight
    ISSUE_I(); ADV_I();
    asm volatile("cp.async.commit_group;" ::: "memory");
    ISSUE_I(); ADV_I();
    asm volatile("cp.async.commit_group;" ::: "memory");

    int st_c = 0;
    for (;;) {
        int lastst = 0;
        for (int cc = 0; cc < nch; cc++) {
            asm volatile("cp.async.wait_group 1;" ::: "memory");
            __syncthreads();
            compute_chunk(sbw + 4u * (st_c * STG_F), lane, wm, wn, acc);
            if (tile_i < ntiles) { ISSUE_I(); }
            ADV_I();
            asm volatile("cp.async.commit_group;" ::: "memory");
            lastst = st_c;
            if (++st_c == NSTAGE) st_c = 0;
        }

        // ---- epilogue: 2 half-column passes staged in freed stage buffer ----
        float* ep = reinterpret_cast<float*>(sm) + lastst * STG_F;
        #pragma unroll
        for (int pass = 0; pass < 2; pass++) {
            __syncthreads();
            if ((wn >> 6) == pass) {
                #pragma unroll
                for (int mt = 0; mt < 4; mt++)
                    #pragma unroll
                    for (int h = 0; h < 2; h++)
                        #pragma unroll
                        for (int nt = 0; nt < 4; nt++)
                            #pragma unroll
                            for (int q = 0; q < 2; q++) {
                                const int m = wm + mt*16 + lq + h*8;
                                const int cl = wn - pass*64 + nt*8 + klo*2 + q;
                                if (CM == 0) ep[cl*132 + m] = acc[mt][nt][h*2 + q];
                                else         ep[m*68 + cl] = acc[mt][nt][h*2 + q];
                            }
            }
            __syncthreads();
            #pragma unroll
            for (int it = 0; it < 8; it++) {
                const int idx = it*256 + tid;
                if (CM == 0) {
                    const int cl = idx >> 5, m4 = (idx & 31) * 4;
                    const int col = pass*64 + cl;
                    const int mg0 = m0C + m4;
                    if (PRED && mg0 >= Mvalid) continue;
                    float4 v4 = *(float4*)&ep[cl*132 + m4];
                    float vv[4] = {v4.x, v4.y, v4.z, v4.w};
                    float4 b4, g4, e4, r4;
                    if (BIAS)  b4 = *(const float4*)(bias + mg0);
                    if (BNORM){ g4 = *(const float4*)(gam + mg0); e4 = *(const float4*)(bet + mg0); }
                    if (RES)   r4 = *(const float4*)(resT + ((size_t)nC*Np + p0C + col)*128 + mg0);
                    const float* bp = (const float*)&b4; const float* gp = (const float*)&g4;
                    const float* epp = (const float*)&e4; const float* rp = (const float*)&r4;
                    float4 o4; float* op = (float*)&o4;
                    #pragma unroll
                    for (int j = 0; j < 4; j++) {
                        float v = vv[j];
                        if (BIAS)  v += bp[j];
                        if (BNORM) v = v * (gp[j] * BN_INV) + epp[j];
                        if (RES)   v += rp[j];
                        if (LRELU) v = v > 0.f ? v : 0.1f * v;
                        op[j] = v;
                    }
                    *(float4*)(Cp + ((size_t)nC*Np + p0C + col)*ldc + mg0) = o4;
                } else {
                    const int m = idx >> 4, c4l = (idx & 15) * 4;
                    const int col = pass*64 + c4l;
                    const int mg = m0C + m;
                    float4 v4 = *(float4*)&ep[m*68 + c4l];
                    float vv[4] = {v4.x, v4.y, v4.z, v4.w};
                    float bi = BIAS ? bias[mg] : 0.f;
                    float sc = BNORM ? gam[mg] * BN_INV : 1.f;
                    float sh = BNORM ? bet[mg] : 0.f;
                    float4 r4;
                    if (CM == 1 && RES)
                        r4 = *(const float4*)(resT + ((size_t)(nC*128 + mg))*TVn + p0C + col);
                    const float* rp = (const float*)&r4;
                    float4 o4; float* op = (float*)&o4;
                    #pragma unroll
                    for (int j = 0; j < 4; j++) {
                        float v = vv[j] + bi;
                        if (BNORM) v = v * sc + sh;
                        if (CM == 1 && RES) v += rp[j];
                        if (LRELU) v = v > 0.f ? v : 0.1f * v;
                        op[j] = v;
                    }
                    if (CM == 1)
                        *(float4*)(Cp + ((size_t)(nC*128 + mg))*TVn + p0C + col) = o4;
                    else
                        *(float4*)(Cp + ((size_t)nC*TVn + (size_t)m*25 + v25C)*512 + s4C*128 + col) = o4;
                }
            }
        }
        __syncthreads();   // epilogue reads done before this stage is re-filled

        tile_c += gridDim.x;
        if (tile_c >= ntiles) break;
        DECODE_C();
        #pragma unroll
        for (int a = 0; a < 4; a++)
            #pragma unroll
            for (int b = 0; b < 4; b++)
                #pragma unroll
                for (int c = 0; c < 4; c++) acc[a][b][c] = 0.f;
    }
#undef ISSUE_I
#undef ADV_I
#undef DECODE_I
#undef DECODE_C
}

// ---------------- prep: ALL weight packs in one launch ----------------
__global__ void pack_all(const float* __restrict__ w_in_s, const float* __restrict__ w_out_s,
                         const float* __restrict__ w_ff_s, const float* __restrict__ w_in_t,
                         const float* __restrict__ w_out_t, const float* __restrict__ w_ff_t,
                         const float* __restrict__ w_tcn)
{
    int idx = blockIdx.x * blockDim.x + threadIdx.x;
    if (idx >= W_TOTAL) return;
    const float* src; int off, Msrc, K, tcn = 0;
    if      (idx < OFF_WOUTS){ src = w_in_s;  off = OFF_WINS;  Msrc = 192; K = 128; }
    else if (idx < OFF_WINT) { if (idx < OFF_WFFS){ src = w_out_s; off = OFF_WOUTS; Msrc = 128; K = 384; }
                               else              { src = w_ff_s;  off = OFF_WFFS;  Msrc = 128; K = 128; } }
    else if (idx < OFF_WOUTT){ src = w_in_t;  off = OFF_WINT;  Msrc = 256; K = 128; }
    else if (idx < OFF_WFFT) { src = w_out_t; off = OFF_WOUTT; Msrc = 128; K = 512; }
    else if (idx < OFF_WTCN) { src = w_ff_t;  off = OFF_WFFT;  Msrc = 128; K = 128; }
    else                     { src = w_tcn;   off = OFF_WTCN;  Msrc = 128; K = 896; tcn = 1; }
    int local = idx - off;
    int mrow = local / K, k = local - mrow * K;
    float v = 0.f;
    if (mrow < Msrc) {
        if (tcn) { int j = k >> 7, c = k & 127; v = src[(mrow * 128 + c) * 7 + j]; }
        else     { v = src[(size_t)mrow * K + k]; }
    }
    g_wp[idx] = __uint_as_float(f2tf32(v));
}

// ---------------- prep: x -> xT (half batch per launch) ----------------
__global__ __launch_bounds__(256) void txpose_x(const float* __restrict__ x, int nbase)
{
    __shared__ float t[32][33];
    int p0 = blockIdx.x * 32, c0 = blockIdx.y * 32, n = nbase + blockIdx.z;
    int tx = threadIdx.x & 31, ty = threadIdx.x >> 5;
    for (int r = ty; r < 32; r += 8)
        t[r][tx] = x[((size_t)n * 128 + c0 + r) * TVn + p0 + tx];
    __syncthreads();
    for (int r = ty; r < 32; r += 8)
        g_xT[(size_t)n * TVn * 128 + (size_t)(p0 + r) * 128 + c0 + tx] = t[tx][r];
}

// ---------------- prep: toT -> tnc (NCHW) ----------------
__global__ __launch_bounds__(256) void txpose_inv()
{
    __shared__ float t[32][33];
    int p0 = blockIdx.x * 32, c0 = blockIdx.y * 32, n = blockIdx.z;
    int tx = threadIdx.x & 31, ty = threadIdx.x >> 5;
    for (int r = ty; r < 32; r += 8)
        t[r][tx] = g_toT[((size_t)n * TVn + p0 + r) * 128 + c0 + tx];
    __syncthreads();
    for (int r = ty; r < 32; r += 8)
        g_tnc[((size_t)n * 128 + c0 + r) * TVn + p0 + tx] = t[tx][r];
}

// ---------------- prep: soT -> tmaj[n][v][c][t] ----------------
__global__ __launch_bounds__(256) void txpose_tmaj()
{
    __shared__ float t[32][33];
    int bt = blockIdx.x;
    int t0 = (bt & 3) * 32, c0 = (bt >> 2) * 32;
    int v = blockIdx.y, n = blockIdx.z;
    int tx = threadIdx.x & 31, ty = threadIdx.x >> 5;
    for (int r = ty; r < 32; r += 8)
        t[r][tx] = g_soT[(size_t)n * TVn * 128 + (size_t)((t0 + r) * 25 + v) * 128 + c0 + tx];
    __syncthreads();
    for (int r = ty; r < 32; r += 8)
        g_tmaj[((size_t)(n * 25 + v) * 128 + c0 + r) * 128 + t0 + tx] = t[tx][r];
}

// ---------------- spatial attention (2u x 2v register tiles, LDS.64) -------------
__global__ __launch_bounds__(256)
void satt_kernel(const float* __restrict__ att0, const float* __restrict__ alphas)
{
    int t = blockIdx.x, s = blockIdx.y, n = blockIdx.z;
    __shared__ float qs[32][26], ks[32][26];
    int tid = threadIdx.x;
    const float* qb = g_qkT + (size_t)n * TVn * 192;
    for (int i = tid; i < 832; i += 256) {
        int row = i >> 5, c = i & 31;
        float qv = 0.f, kv = 0.f;
        if (row < 25) {
            qv = qb[(size_t)(t * 25 + row) * 192 + s * 32 + c];
            kv = qb[(size_t)(t * 25 + row) * 192 + 96 + s * 32 + c];
        }
        qs[c][row] = qv;
        ks[c][row] = kv;
    }
    __syncthreads();
    float alpha = alphas[s];
    float* ob = g_atts + (((size_t)(n * 3 + s)) * 128 + t) * 704;
    if (tid < 169) {
        int ti = tid / 13, tj = tid % 13;
        int u0 = ti * 2, v0 = tj * 2;
        float s00 = 0.f, s01 = 0.f, s10 = 0.f, s11 = 0.f;
        #pragma unroll
        for (int c = 0; c < 32; c++) {
            float2 q2 = *(const float2*)&qs[c][u0];
            float2 k2 = *(const float2*)&ks[c][v0];
            s00 += q2.x * k2.x; s01 += q2.x * k2.y;
            s10 += q2.y * k2.x; s11 += q2.y * k2.y;
        }
        float b00 = att0[s * 625 + u0 * 25 + v0];
        float b01 = (v0 + 1 < 25) ? att0[s * 625 + u0 * 25 + v0 + 1] : 0.f;
        float2 o0, o1;
        o0.x = b00 + tanh_ap(s00 * (1.f / 32.f)) * alpha;
        o0.y = (v0 + 1 < 25) ? b01 + tanh_ap(s01 * (1.f / 32.f)) * alpha : 0.f;
        *(float2*)&ob[u0 * 28 + v0] = o0;
        if (u0 + 1 < 25) {
            float b10 = att0[s * 625 + (u0 + 1) * 25 + v0];
            float b11 = (v0 + 1 < 25) ? att0[s * 625 + (u0 + 1) * 25 + v0 + 1] : 0.f;
            o1.x = b10 + tanh_ap(s10 * (1.f / 32.f)) * alpha;
            o1.y = (v0 + 1 < 25) ? b11 + tanh_ap(s11 * (1.f / 32.f)) * alpha : 0.f;
            *(float2*)&ob[(u0 + 1) * 28 + v0] = o1;
        }
    } else if (tid >= 169 && tid < 194) {
        int u = tid - 169;
        *(float2*)&ob[u * 28 + 26] = make_float2(0.f, 0.f);
    }
}

// ---------------- spatial mix -> yT (float4 attention reads) ----------------
__global__ __launch_bounds__(128)
void ymix_kernel()
{
    int t = blockIdx.x, s = blockIdx.y, n = blockIdx.z;
    __shared__ float4 a4[25][7];
    int c = threadIdx.x;
    const float4* ab4 = (const float4*)(g_atts + (((size_t)(n * 3 + s)) * 128 + t) * 704);
    for (int i = c; i < 175; i += 128) a4[i / 7][i % 7] = ab4[i];
    __syncthreads();
    float xr[25];
    const float* xb = g_xT + (size_t)n * TVn * 128 + (size_t)(t * 25) * 128 + c;
    #pragma unroll
    for (int u = 0; u < 25; u++) xr[u] = xb[u * 128];
    float4 acc[7];
    #pragma unroll
    for (int g = 0; g < 7; g++) acc[g] = make_float4(0.f, 0.f, 0.f, 0.f);
    #pragma unroll
    for (int u = 0; u < 25; u++) {
        float xu = xr[u];
        #pragma unroll
        for (int g = 0; g < 7; g++) {
            float4 av = a4[u][g];
            acc[g].x += xu * av.x; acc[g].y += xu * av.y;
            acc[g].z += xu * av.z; acc[g].w += xu * av.w;
        }
    }
    float* yb = g_yT + (size_t)n * TVn * 384 + (size_t)(t * 25) * 384 + s * 128 + c;
    #pragma unroll
    for (int g = 0; g < 7; g++) {
        const float* ap = (const float*)&acc[g];
        #pragma unroll
        for (int j = 0; j < 4; j++) {
            int v = g * 4 + j;
            if (v < 25) yb[(size_t)v * 384] = ap[j];
        }
    }
}

// ---------------- mean over V (sout -> sbar[n][t][c]) ----------------
__global__ void meanv_kernel()
{
    int i = blockIdx.x * blockDim.x + threadIdx.x;
    if (i >= NB * 128 * 128) return;
    int c = i & 127, t = (i >> 7) & 127, n = i >> 14;
    const float* b = g_soT + (size_t)n * TVn * 128 + (size_t)(t * 25) * 128 + c;
    float sum = 0.f;
    #pragma unroll
    for (int v = 0; v < 25; v++) sum += b[v * 128];
    g_sbar[(size_t)n * 16384 + t * 128 + c] = sum * (1.f / 25.f);
}

// ---------------- temporal attention -> att[u][t] (u-split 4x) ----------------
__global__ __launch_bounds__(256)
void tatt_kernel(const float* __restrict__ af, const float* __restrict__ ab)
{
    int bz = blockIdx.x;            // n*16 + s*4 + ug
    int n = bz >> 4, s = (bz >> 2) & 3, ug = bz & 3;
    __shared__ float qs[32][129], ksu[32][32];
    int tid = threadIdx.x;
    const float* base = g_qtm + (size_t)n * 32768;   // [t][256]
    for (int i = tid; i < 4096; i += 256) {
        int t = i >> 5, c = i & 31;
        qs[c][t] = base[t * 256 + s * 32 + c];
    }
    for (int i = tid; i < 1024; i += 256) {
        int ul = i >> 5, c = i & 31;
        ksu[c][ul] = base[(ug * 32 + ul) * 256 + 128 + s * 32 + c];
    }
    __syncthreads();
    float alpha = (s < 2) ? af[s] : ab[s - 2];
    float* ob = g_att + ((size_t)(n * 4 + s)) * 16384;
    for (int idx = tid; idx < 4096; idx += 256) {
        int ul = idx >> 7, t = idx & 127;
        int u = ug * 32 + ul;
        float sum = 0.f;
        #pragma unroll
        for (int c = 0; c < 32; c++) sum += qs[c][t] * ksu[c][ul];
        float v = tanh_ap(sum * (1.f / 32.f)) * alpha;
        bool keep = (s < 2) ? (t >= u) : (u >= t);
        ob[u * 128 + t] = keep ? v : 0.f;
    }
}

// ---------------- host launcher ----------------
static inline int pgrid(int tiles){ return tiles < PGRID ? tiles : PGRID; }

extern "C" void kernel_launch(void* const* d_in, const int* in_sizes, int n_in,
                              void* d_out, int out_size)
{
    const float* x       = (const float*)d_in[0];
    const float* w_in_s  = (const float*)d_in[1];
    const float* b_in_s  = (const float*)d_in[2];
    const float* att0s   = (const float*)d_in[3];
    const float* alphas  = (const float*)d_in[4];
    const float* w_out_s = (const float*)d_in[5];
    const float* b_out_s = (const float*)d_in[6];
    const float* g_out_s = (const float*)d_in[7];
    const float* be_out_s= (const float*)d_in[8];
    const float* w_ff_s  = (const float*)d_in[9];
    const float* b_ff_s  = (const float*)d_in[10];
    const float* g_ff_s  = (const float*)d_in[11];
    const float* be_ff_s = (const float*)d_in[12];
    const float* w_in_t  = (const float*)d_in[13];
    const float* b_in_t  = (const float*)d_in[14];
    const float* al_f    = (const float*)d_in[15];
    const float* al_b    = (const float*)d_in[16];
    const float* w_out_t = (const float*)d_in[17];
    const float* b_out_t = (const float*)d_in[18];
    const float* g_out_t = (const float*)d_in[19];
    const float* be_out_t= (const float*)d_in[20];
    const float* w_ff_t  = (const float*)d_in[21];
    const float* b_ff_t  = (const float*)d_in[22];
    const float* g_ff_t  = (const float*)d_in[23];
    const float* be_ff_t = (const float*)d_in[24];
    const float* w_tcn   = (const float*)d_in[25];
    const float* b_tcn   = (const float*)d_in[26];
    const float* g_tcn   = (const float*)d_in[27];
    const float* be_tcn  = (const float*)d_in[28];
    float* out = (float*)d_out;

    float *wp, *xT, *qkT, *yT, *s1T, *soT, *sbar, *qtm, *att, *tmaj, *zT, *toT, *tnc;
    cudaGetSymbolAddress((void**)&wp,   g_wp);
    cudaGetSymbolAddress((void**)&xT,   g_xT);
    cudaGetSymbolAddress((void**)&qkT,  g_qkT);
    cudaGetSymbolAddress((void**)&yT,   g_yT);
    cudaGetSymbolAddress((void**)&s1T,  g_s1T);
    cudaGetSymbolAddress((void**)&soT,  g_soT);
    cudaGetSymbolAddress((void**)&sbar, g_sbar);
    cudaGetSymbolAddress((void**)&qtm,  g_qtm);
    cudaGetSymbolAddress((void**)&att,  g_att);
    cudaGetSymbolAddress((void**)&tmaj, g_tmaj);
    cudaGetSymbolAddress((void**)&zT,   g_zT);
    cudaGetSymbolAddress((void**)&toT,  g_toT);
    cudaGetSymbolAddress((void**)&tnc,  g_tnc);

    auto G1 = mma_gemm<0,0,0,true,false,false,false,true>;   // qk (padded M)
    auto G2 = mma_gemm<0,0,0,true,true,true,true,false>;     // bn+res+lrelu, transposed out
    auto G3 = mma_gemm<0,0,0,true,false,false,false,false>;  // plain bias (qtm)
    auto G4 = mma_gemm<1,0,2,false,false,false,false,false>; // temporal mix
    auto G5 = mma_gemm<0,1,1,true,true,true,true,false>;     // TCN final, NCHW out
    cudaFuncSetAttribute(G1, cudaFuncAttributeMaxDynamicSharedMemorySize, SMEMSZ);
    cudaFuncSetAttribute(G2, cudaFuncAttributeMaxDynamicSharedMemorySize, SMEMSZ);
    cudaFuncSetAttribute(G3, cudaFuncAttributeMaxDynamicSharedMemorySize, SMEMSZ);
    cudaFuncSetAttribute(G4, cudaFuncAttributeMaxDynamicSharedMemorySize, SMEMSZ);
    cudaFuncSetAttribute(G5, cudaFuncAttributeMaxDynamicSharedMemorySize, SMEMSZ);

    // [0] pack all weights, [1][2] transpose x (two halves)
    pack_all<<<(W_TOTAL+255)/256,256>>>(w_in_s, w_out_s, w_ff_s, w_in_t, w_out_t, w_ff_t, w_tcn);
    txpose_x<<<dim3(100,4,16),256>>>(x, 0);
    txpose_x<<<dim3(100,4,16),256>>>(x, 16);

    // [3] qk = W_in_s @ x + b   tiles=25*2*32  <- ncu profiles this
    G1<<<pgrid(1600),256,SMEMSZ>>>(wp+OFF_WINS, xT, qkT,
        b_in_s, nullptr, nullptr, nullptr, 128, 128, 192, 192, 4, TVn, 1600, 25, 50);

    // [4] spatial attention, [5] spatial mix
    satt_kernel<<<dim3(128,3,NB),256>>>(att0s, alphas);
    ymix_kernel<<<dim3(128,3,NB),128>>>();

    // [6] s1 = lrelu(x + bn(W_out_s @ y + b))   K=384, tiles=25*1*32
    G2<<<pgrid(800),256,SMEMSZ>>>(wp+OFF_WOUTS, yT, s1T,
        b_out_s, g_out_s, be_out_s, xT, 384, 384, 128, 128, 12, TVn, 800, 25, 25);

    // [7] sout = lrelu(x + bn(W_ff_s @ s1 + b))
    G2<<<pgrid(800),256,SMEMSZ>>>(wp+OFF_WFFS, s1T, soT,
        b_ff_s, g_ff_s, be_ff_s, xT, 128, 128, 128, 128, 4, TVn, 800, 25, 25);

    // [8] mean over v, [9] qtm = W_in_t @ sbar + b  tiles=1*2*32
    meanv_kernel<<<(NB*128*128+255)/256,256>>>();
    G3<<<pgrid(64),256,SMEMSZ>>>(wp+OFF_WINT, sbar, qtm,
        b_in_t, nullptr, nullptr, nullptr, 128, 128, 256, 256, 4, 128, 64, 1, 2);

    // [10] temporal attention
    tatt_kernel<<<NB*16,256>>>(al_f, al_b);

    // [11] sout -> tmaj
    txpose_tmaj<<<dim3(16,25,NB),256>>>();

    // [12] z (temporal mix) per (n,s,v)  tiles=3200
    G4<<<pgrid(3200),256,SMEMSZ>>>(att, tmaj, zT,
        nullptr, nullptr, nullptr, nullptr, 128, 128, 512, 128, 4, TVn, 3200, 1, 1);

    // [13] t1 = lrelu(sout + bn(W_out_t @ z + b))   K=512
    G2<<<pgrid(800),256,SMEMSZ>>>(wp+OFF_WOUTT, zT, s1T,
        b_out_t, g_out_t, be_out_t, soT, 512, 512, 128, 128, 16, TVn, 800, 25, 25);

    // [14] tout = lrelu(sout + bn(W_ff_t @ t1 + b))
    G2<<<pgrid(800),256,SMEMSZ>>>(wp+OFF_WFFT, s1T, toT,
        b_ff_t, g_ff_t, be_ff_t, soT, 128, 128, 128, 128, 4, TVn, 800, 25, 25);

    // [15] toT -> NCHW copy for final residual
    txpose_inv<<<dim3(100,4,NB),256>>>();

    // [16] out = lrelu(tout + bn(tcn7(tout)+b))   K=896 im2col
    G5<<<pgrid(800),256,SMEMSZ>>>(wp+OFF_WTCN, toT, out,
        b_tcn, g_tcn, be_tcn, tnc, 896, 128, 128, 128, 28, TVn, 800, 25, 25);
}

// round 13
// speedup vs baseline: 1.1672x; 1.1672x over previous
#include <cuda_runtime.h>
#include <cstdint>
#include <math.h>

#define NB 32
#define TVn 3200
#define BN_INV 0.9999950000374997f

// ---------------- scratch ----------------
__device__ float g_wp  [327680];
__device__ float g_xT  [(size_t)NB*TVn*128];
__device__ float g_qkT [(size_t)NB*TVn*192];
__device__ float g_atts[(size_t)NB*3*128*704];
__device__ float g_yT  [(size_t)NB*TVn*384];
__device__ float g_s1T [(size_t)NB*TVn*128];
__device__ float g_soT [(size_t)NB*TVn*128];
__device__ float g_sbar[(size_t)NB*128*128];
__device__ float g_qtm [(size_t)NB*128*256];
__device__ float g_att [(size_t)NB*4*128*128];
__device__ float g_tmaj[(size_t)NB*25*128*128];
__device__ float g_zT  [(size_t)NB*TVn*512];
__device__ float g_toT [(size_t)NB*TVn*128];
__device__ float g_tnc [(size_t)NB*128*TVn];

#define OFF_WINS  0
#define OFF_WOUTS 32768
#define OFF_WFFS  81920
#define OFF_WINT  98304
#define OFF_WOUTT 131072
#define OFF_WFFT  196608
#define OFF_WTCN  212992
#define W_TOTAL   327680

// narrow kernel smem (R11 geometry)
#define RS     36
#define BOFF_F 4608
#define STG_F  9216
#define NSTAGE 3
#define SMEMSZ (STG_F * NSTAGE * 4)     // 110592 B

// wide kernel smem: A 128 rows + B 256 rows, RS stride
#define BOFFW_F 4608                     // 128*36
#define STGW_F  13824                    // 384*36
#define SMEMW   (STGW_F * NSTAGE * 4)    // 165888 B

// ---------------- helpers ----------------
__device__ __forceinline__ uint32_t smem_u32(const void* p){
    uint32_t a;
    asm("{ .reg .u64 t; cvta.to.shared.u64 t, %1; cvt.u32.u64 %0, t; }" : "=r"(a) : "l"(p));
    return a;
}
__device__ __forceinline__ uint32_t f2tf32(float f){
    uint32_t r; asm("cvt.rna.tf32.f32 %0, %1;" : "=r"(r) : "f"(f)); return r;
}
__device__ __forceinline__ float tanh_ap(float x){
    float r; asm("tanh.approx.f32 %0, %1;" : "=f"(r) : "f"(x)); return r;
}
__device__ __forceinline__ void mma_tf32(float* d, const uint32_t* a, const uint32_t* b){
    asm volatile("mma.sync.aligned.m16n8k8.row.col.f32.tf32.tf32.f32 "
        "{%0,%1,%2,%3}, {%4,%5,%6,%7}, {%8,%9}, {%0,%1,%2,%3};"
        : "+f"(d[0]), "+f"(d[1]), "+f"(d[2]), "+f"(d[3])
        : "r"(a[0]), "r"(a[1]), "r"(a[2]), "r"(a[3]), "r"(b[0]), "r"(b[1]));
}

// ================= narrow kernel (R11, unchanged) =================
__device__ __forceinline__ void compute_chunk(uint32_t stage_b, int lane,
                                              int wm, int wn, float acc[4][4][4]){
    const int arow = (lane & 7) + ((lane >> 3) & 1) * 8;
    const uint32_t aoff = ((lane >> 4) & 1) * 16;
    const int brow = lane & 7;
    const uint32_t boff = ((lane >> 3) & 1) * 16;
    const uint32_t abase = stage_b + (uint32_t)((wm + arow) * RS) * 4u + aoff;
    const uint32_t bbase = stage_b + (uint32_t)(BOFF_F + (wn + brow) * RS) * 4u + boff;
    #pragma unroll
    for (int k8 = 0; k8 < 4; k8++){
        uint32_t af[4][4], bf[4][2];
        #pragma unroll
        for (int mt = 0; mt < 4; mt++){
            uint32_t ad = abase + (uint32_t)(mt * 16 * RS) * 4u + k8 * 32;
            asm volatile("ldmatrix.sync.aligned.m8n8.x4.shared.b16 {%0,%1,%2,%3}, [%4];"
                : "=r"(af[mt][0]), "=r"(af[mt][1]), "=r"(af[mt][2]), "=r"(af[mt][3])
                : "r"(ad));
        }
        #pragma unroll
        for (int nt = 0; nt < 4; nt++){
            uint32_t bd = bbase + (uint32_t)(nt * 8 * RS) * 4u + k8 * 32;
            asm volatile("ldmatrix.sync.aligned.m8n8.x2.shared.b16 {%0,%1}, [%2];"
                : "=r"(bf[nt][0]), "=r"(bf[nt][1])
                : "r"(bd));
        }
        #pragma unroll
        for (int mt = 0; mt < 4; mt++)
            #pragma unroll
            for (int nt = 0; nt < 4; nt++)
                mma_tf32(acc[mt][nt], af[mt], bf[nt]);
    }
}

template<int ZMODE,int BSHIFT,int CM,bool BIAS,bool BNORM,bool RES,bool LRELU,bool PRED>
__global__ __launch_bounds__(256,2)
void mma_gemm(const float* __restrict__ A, const float* __restrict__ Bp,
              float* __restrict__ Cp,
              const float* __restrict__ bias, const float* __restrict__ gam,
              const float* __restrict__ bet, const float* __restrict__ resT,
              int Ka, int Bld, int ldc, int Mvalid, int nch, int Np)
{
    extern __shared__ uint32_t sm[];
    const uint32_t sbw = smem_u32(sm);
    const int tid = threadIdx.x, lane = tid & 31, wid = tid >> 5;
    const int wm = (wid >> 2) * 64, wn = (wid & 3) * 32;
    const int lq = lane >> 2, klo = lane & 3;

    int n, s4 = 0, v25 = 0;
    if (ZMODE == 0) { n = blockIdx.z; }
    else { int bz = blockIdx.z; n = bz / 100; int rr = bz % 100; s4 = rr / 25; v25 = rr % 25; }
    const int m0 = blockIdx.y * 128;
    const int p0 = (ZMODE == 0) ? blockIdx.x * 128 : 0;
    const float* Ab = (ZMODE == 0) ? A : A + (size_t)(n*4 + s4) * 16384;
    const float* Bb = (ZMODE == 0) ? Bp + (size_t)n * Np * Bld
                                   : Bp + (size_t)(n*25 + v25) * 16384;

    const int r = tid & 127, kh = (tid >> 7) * 16;
    const float* parow = Ab + (size_t)(m0 + r) * Ka + kh;

    float acc[4][4][4];
    #pragma unroll
    for (int a = 0; a < 4; a++)
        #pragma unroll
        for (int b = 0; b < 4; b++)
            #pragma unroll
            for (int c = 0; c < 4; c++) acc[a][b][c] = 0.f;

#define ISSUE(cc, stg) {                                                         \
        const int k0_ = (cc) * 32;                                               \
        int k0B_, grow_;                                                         \
        if (BSHIFT){ int j_ = (cc) >> 2; k0B_ = ((cc) & 3) * 32;                 \
                     grow_ = p0 + r + (j_ - 3) * 25; }                           \
        else { k0B_ = k0_; grow_ = p0 + r; }                                     \
        const bool ok_ = (!BSHIFT) || ((unsigned)grow_ < (unsigned)TVn);         \
        const int bsz_ = ok_ ? 16 : 0;                                           \
        const float* asrc_ = parow + k0_;                                        \
        const float* bsrc_ = Bb + (size_t)(ok_ ? grow_ : 0) * Bld + k0B_ + kh;   \
        const uint32_t ad_ = sbw + 4u * ((stg) * STG_F + r * RS + kh);           \
        const uint32_t bd_ = sbw + 4u * ((stg) * STG_F + BOFF_F + r * RS + kh);  \
        _Pragma("unroll")                                                        \
        for (int i = 0; i < 4; i++){                                             \
            asm volatile("cp.async.cg.shared.global [%0], [%1], 16;"             \
                         :: "r"(ad_ + 16u*i), "l"(asrc_ + i*4) : "memory");      \
            asm volatile("cp.async.cg.shared.global [%0], [%1], 16, %2;"         \
                         :: "r"(bd_ + 16u*i), "l"(bsrc_ + i*4), "r"(bsz_) : "memory"); \
        } }

    ISSUE(0, 0)
    asm volatile("cp.async.commit_group;" ::: "memory");
    ISSUE(1, 1)
    asm volatile("cp.async.commit_group;" ::: "memory");

    for (int c = 0; c < nch; c++) {
        asm volatile("cp.async.wait_group 1;" ::: "memory");
        __syncthreads();
        compute_chunk(sbw + 4u * ((c % NSTAGE) * STG_F), lane, wm, wn, acc);
        const int nc = c + 2;
        if (nc < nch) { ISSUE(nc, nc % NSTAGE) }
        asm volatile("cp.async.commit_group;" ::: "memory");
    }
#undef ISSUE

    asm volatile("cp.async.wait_group 0;" ::: "memory");
    __syncthreads();
    float* smf = reinterpret_cast<float*>(sm);

    #pragma unroll
    for (int mt = 0; mt < 4; mt++)
        #pragma unroll
        for (int h = 0; h < 2; h++)
            #pragma unroll
            for (int nt = 0; nt < 4; nt++)
                #pragma unroll
                for (int q = 0; q < 2; q++) {
                    const int m = wm + mt*16 + lq + h*8;
                    const int col = wn + nt*8 + klo*2 + q;
                    if (CM == 0) smf[col*132 + m] = acc[mt][nt][h*2 + q];
                    else         smf[m*132 + col] = acc[mt][nt][h*2 + q];
                }
    __syncthreads();

    #pragma unroll
    for (int it = 0; it < 16; it++) {
        const int idx = it*256 + tid;
        if (CM == 0) {
            const int col = idx >> 5, m4 = (idx & 31) * 4;
            const int mg0 = m0 + m4;
            if (PRED && mg0 >= Mvalid) continue;
            float4 v4 = *(float4*)&smf[col*132 + m4];
            float vv[4] = {v4.x, v4.y, v4.z, v4.w};
            float4 b4, g4, e4, r4;
            if (BIAS)  b4 = *(const float4*)(bias + mg0);
            if (BNORM){ g4 = *(const float4*)(gam + mg0); e4 = *(const float4*)(bet + mg0); }
            if (RES)   r4 = *(const float4*)(resT + ((size_t)n*Np + p0 + col)*128 + mg0);
            const float* bp = (const float*)&b4; const float* gp = (const float*)&g4;
            const float* ep = (const float*)&e4; const float* rp = (const float*)&r4;
            float4 o4; float* op = (float*)&o4;
            #pragma unroll
            for (int j = 0; j < 4; j++) {
                float v = vv[j];
                if (BIAS)  v += bp[j];
                if (BNORM) v = v * (gp[j] * BN_INV) + ep[j];
                if (RES)   v += rp[j];
                if (LRELU) v = v > 0.f ? v : 0.1f * v;
                op[j] = v;
            }
            *(float4*)(Cp + ((size_t)n*Np + p0 + col)*ldc + mg0) = o4;
        } else {
            const int m = idx >> 5, c4 = (idx & 31) * 4;
            const int mg = m0 + m;
            float4 v4 = *(float4*)&smf[m*132 + c4];
            float vv[4] = {v4.x, v4.y, v4.z, v4.w};
            float bi = BIAS ? bias[mg] : 0.f;
            float sc = BNORM ? gam[mg] * BN_INV : 1.f;
            float sh = BNORM ? bet[mg] : 0.f;
            float4 r4;
            if (CM == 1 && RES)
                r4 = *(const float4*)(resT + ((size_t)(n*128 + mg))*TVn + p0 + c4);
            const float* rp = (const float*)&r4;
            float4 o4; float* op = (float*)&o4;
            #pragma unroll
            for (int j = 0; j < 4; j++) {
                float v = vv[j] + bi;
                if (BNORM) v = v * sc + sh;
                if (CM == 1 && RES) v += rp[j];
                if (LRELU) v = v > 0.f ? v : 0.1f * v;
                op[j] = v;
            }
            if (CM == 1)
                *(float4*)(Cp + ((size_t)(n*128 + mg))*TVn + p0 + c4) = o4;
            else
                *(float4*)(Cp + ((size_t)n*TVn + (size_t)m*25 + v25)*512 + s4*128 + c4) = o4;
        }
    }
}

// ================= wide kernel: 128M x 256N, 512 threads =================
__device__ __forceinline__ void compute_chunk_w(uint32_t stage_b, int lane,
                                                int wm, int wn, float acc[2][8][4]){
    const int arow = (lane & 7) + ((lane >> 3) & 1) * 8;
    const uint32_t aoff = ((lane >> 4) & 1) * 16;
    const int brow = (lane & 7) + ((lane >> 4) & 1) * 8;
    const uint32_t boff = ((lane >> 3) & 1) * 16;
    const uint32_t abase = stage_b + (uint32_t)((wm + arow) * RS) * 4u + aoff;
    const uint32_t bbase = stage_b + (uint32_t)(BOFFW_F + (wn + brow) * RS) * 4u + boff;
    #pragma unroll
    for (int k8 = 0; k8 < 4; k8++){
        uint32_t af[2][4], bf[8][2];
        #pragma unroll
        for (int mt = 0; mt < 2; mt++){
            uint32_t ad = abase + (uint32_t)(mt * 16 * RS) * 4u + k8 * 32;
            asm volatile("ldmatrix.sync.aligned.m8n8.x4.shared.b16 {%0,%1,%2,%3}, [%4];"
                : "=r"(af[mt][0]), "=r"(af[mt][1]), "=r"(af[mt][2]), "=r"(af[mt][3])
                : "r"(ad));
        }
        #pragma unroll
        for (int ng = 0; ng < 4; ng++){
            uint32_t bd = bbase + (uint32_t)(ng * 16 * RS) * 4u + k8 * 32;
            asm volatile("ldmatrix.sync.aligned.m8n8.x4.shared.b16 {%0,%1,%2,%3}, [%4];"
                : "=r"(bf[2*ng][0]), "=r"(bf[2*ng][1]), "=r"(bf[2*ng+1][0]), "=r"(bf[2*ng+1][1])
                : "r"(bd));
        }
        #pragma unroll
        for (int mt = 0; mt < 2; mt++)
            #pragma unroll
            for (int nt = 0; nt < 8; nt++)
                mma_tf32(acc[mt][nt], af[mt], bf[nt]);
    }
}

template<int BSHIFT,int CM,bool BIAS,bool BNORM,bool RES,bool LRELU,bool PRED>
__global__ __launch_bounds__(512,1)
void mma_gemm_w(const float* __restrict__ A, const float* __restrict__ Bp,
                float* __restrict__ Cp,
                const float* __restrict__ bias, const float* __restrict__ gam,
                const float* __restrict__ bet, const float* __restrict__ resT,
                int Ka, int Bld, int ldc, int Mvalid, int nch, int Np)
{
    extern __shared__ uint32_t sm[];
    const uint32_t sbw = smem_u32(sm);
    const int tid = threadIdx.x, lane = tid & 31, wid = tid >> 5;
    const int wm = (wid >> 2) * 32, wn = (wid & 3) * 64;
    const int lq = lane >> 2, klo = lane & 3;

    const int n = blockIdx.z;
    const int m0 = blockIdx.y * 128;
    const int p0 = blockIdx.x * 256;
    const float* Bb = Bp + (size_t)n * Np * Bld;

    float acc[2][8][4];
    #pragma unroll
    for (int a = 0; a < 2; a++)
        #pragma unroll
        for (int b = 0; b < 8; b++)
            #pragma unroll
            for (int c = 0; c < 4; c++) acc[a][b][c] = 0.f;

    // loader: 6 slots/thread; slot -> row (0..383: 0-127 A, 128-383 B), seg (16B)
#define ISSUEW(cc, stg) {                                                        \
        const int k0_ = (cc) * 32;                                               \
        int k0B_, sh_;                                                           \
        if (BSHIFT){ int j_ = (cc) >> 2; k0B_ = ((cc) & 3) * 32; sh_ = (j_-3)*25;}\
        else { k0B_ = k0_; sh_ = 0; }                                            \
        _Pragma("unroll")                                                        \
        for (int i = 0; i < 6; i++){                                             \
            const int slot_ = tid + i * 512;                                     \
            const int row_ = slot_ >> 3, seg_ = slot_ & 7;                       \
            const uint32_t dst_ = sbw + 4u * ((stg) * STGW_F + row_ * RS + seg_ * 4); \
            if (row_ < 128) {                                                    \
                const float* src_ = A + (size_t)(m0 + row_) * Ka + k0_ + seg_ * 4; \
                asm volatile("cp.async.cg.shared.global [%0], [%1], 16;"         \
                             :: "r"(dst_), "l"(src_) : "memory");                \
            } else {                                                             \
                const int br_ = row_ - 128;                                      \
                const int gb_ = p0 + br_;                                        \
                const int grow_ = gb_ + sh_;                                     \
                const bool ok_ = ((unsigned)gb_ < (unsigned)Np) &&               \
                                 ((unsigned)grow_ < (unsigned)TVn);              \
                const int bsz_ = ok_ ? 16 : 0;                                   \
                const float* src_ = Bb + (size_t)(ok_ ? grow_ : 0) * Bld + k0B_ + seg_ * 4; \
                asm volatile("cp.async.cg.shared.global [%0], [%1], 16, %2;"     \
                             :: "r"(dst_), "l"(src_), "r"(bsz_) : "memory");     \
            } } }

    ISSUEW(0, 0)
    asm volatile("cp.async.commit_group;" ::: "memory");
    ISSUEW(1, 1)
    asm volatile("cp.async.commit_group;" ::: "memory");

    for (int c = 0; c < nch; c++) {
        asm volatile("cp.async.wait_group 1;" ::: "memory");
        __syncthreads();
        compute_chunk_w(sbw + 4u * ((c % NSTAGE) * STGW_F), lane, wm, wn, acc);
        const int nc = c + 2;
        if (nc < nch) { ISSUEW(nc, nc % NSTAGE) }
        asm volatile("cp.async.commit_group;" ::: "memory");
    }
#undef ISSUEW

    asm volatile("cp.async.wait_group 0;" ::: "memory");
    float* ep = reinterpret_cast<float*>(sm);   // reuse stage 0

    #pragma unroll
    for (int pass = 0; pass < 4; pass++) {
        __syncthreads();
        if ((wid & 3) == pass) {
            #pragma unroll
            for (int mt = 0; mt < 2; mt++)
                #pragma unroll
                for (int h = 0; h < 2; h++)
                    #pragma unroll
                    for (int nt = 0; nt < 8; nt++)
                        #pragma unroll
                        for (int q = 0; q < 2; q++) {
                            const int m = wm + mt*16 + lq + h*8;
                            const int cl = nt*8 + klo*2 + q;
                            if (CM == 0) ep[cl*132 + m] = acc[mt][nt][h*2 + q];
                            else         ep[m*68 + cl] = acc[mt][nt][h*2 + q];
                        }
        }
        __syncthreads();
        #pragma unroll
        for (int it = 0; it < 4; it++) {
            const int idx = it*512 + tid;
            if (CM == 0) {
                const int cl = idx >> 5, m4 = (idx & 31) * 4;
                const int col = pass*64 + cl;
                const int mg0 = m0 + m4;
                if (PRED && mg0 >= Mvalid) continue;
                if (p0 + col >= Np) continue;
                float4 v4 = *(float4*)&ep[cl*132 + m4];
                float vv[4] = {v4.x, v4.y, v4.z, v4.w};
                float4 b4, g4, e4, r4;
                if (BIAS)  b4 = *(const float4*)(bias + mg0);
                if (BNORM){ g4 = *(const float4*)(gam + mg0); e4 = *(const float4*)(bet + mg0); }
                if (RES)   r4 = *(const float4*)(resT + ((size_t)n*Np + p0 + col)*128 + mg0);
                const float* bp = (const float*)&b4; const float* gp = (const float*)&g4;
                const float* epp = (const float*)&e4; const float* rp = (const float*)&r4;
                float4 o4; float* op = (float*)&o4;
                #pragma unroll
                for (int j = 0; j < 4; j++) {
                    float v = vv[j];
                    if (BIAS)  v += bp[j];
                    if (BNORM) v = v * (gp[j] * BN_INV) + epp[j];
                    if (RES)   v += rp[j];
                    if (LRELU) v = v > 0.f ? v : 0.1f * v;
                    op[j] = v;
                }
                *(float4*)(Cp + ((size_t)n*Np + p0 + col)*ldc + mg0) = o4;
            } else {
                const int m = idx >> 4, c4l = (idx & 15) * 4;
                const int col = pass*64 + c4l;
                const int mg = m0 + m;
                if (p0 + col >= Np) continue;
                float4 v4 = *(float4*)&ep[m*68 + c4l];
                float vv[4] = {v4.x, v4.y, v4.z, v4.w};
                float bi = BIAS ? bias[mg] : 0.f;
                float sc = BNORM ? gam[mg] * BN_INV : 1.f;
                float sh = BNORM ? bet[mg] : 0.f;
                float4 r4;
                if (RES) r4 = *(const float4*)(resT + ((size_t)(n*128 + mg))*TVn + p0 + col);
                const float* rp = (const float*)&r4;
                float4 o4; float* op = (float*)&o4;
                #pragma unroll
                for (int j = 0; j < 4; j++) {
                    float v = vv[j] + bi;
                    if (BNORM) v = v * sc + sh;
                    if (RES)   v += rp[j];
                    if (LRELU) v = v > 0.f ? v : 0.1f * v;
                    op[j] = v;
                }
                *(float4*)(Cp + ((size_t)(n*128 + mg))*TVn + p0 + col) = o4;
            }
        }
    }
}

// ---------------- prep kernels ----------------
__global__ void pack_all(const float* __restrict__ w_in_s, const float* __restrict__ w_out_s,
                         const float* __restrict__ w_ff_s, const float* __restrict__ w_in_t,
                         const float* __restrict__ w_out_t, const float* __restrict__ w_ff_t,
                         const float* __restrict__ w_tcn)
{
    int idx = blockIdx.x * blockDim.x + threadIdx.x;
    if (idx >= W_TOTAL) return;
    const float* src; int off, Msrc, K, tcn = 0;
    if      (idx < OFF_WOUTS){ src = w_in_s;  off = OFF_WINS;  Msrc = 192; K = 128; }
    else if (idx < OFF_WINT) { if (idx < OFF_WFFS){ src = w_out_s; off = OFF_WOUTS; Msrc = 128; K = 384; }
                               else              { src = w_ff_s;  off = OFF_WFFS;  Msrc = 128; K = 128; } }
    else if (idx < OFF_WOUTT){ src = w_in_t;  off = OFF_WINT;  Msrc = 256; K = 128; }
    else if (idx < OFF_WFFT) { src = w_out_t; off = OFF_WOUTT; Msrc = 128; K = 512; }
    else if (idx < OFF_WTCN) { src = w_ff_t;  off = OFF_WFFT;  Msrc = 128; K = 128; }
    else                     { src = w_tcn;   off = OFF_WTCN;  Msrc = 128; K = 896; tcn = 1; }
    int local = idx - off;
    int mrow = local / K, k = local - mrow * K;
    float v = 0.f;
    if (mrow < Msrc) {
        if (tcn) { int j = k >> 7, c = k & 127; v = src[(mrow * 128 + c) * 7 + j]; }
        else     { v = src[(size_t)mrow * K + k]; }
    }
    g_wp[idx] = __uint_as_float(f2tf32(v));
}

__global__ __launch_bounds__(256) void txpose_x(const float* __restrict__ x, int nbase)
{
    __shared__ float t[32][33];
    int p0 = blockIdx.x * 32, c0 = blockIdx.y * 32, n = nbase + blockIdx.z;
    int tx = threadIdx.x & 31, ty = threadIdx.x >> 5;
    for (int r = ty; r < 32; r += 8)
        t[r][tx] = x[((size_t)n * 128 + c0 + r) * TVn + p0 + tx];
    __syncthreads();
    for (int r = ty; r < 32; r += 8)
        g_xT[(size_t)n * TVn * 128 + (size_t)(p0 + r) * 128 + c0 + tx] = t[tx][r];
}

__global__ __launch_bounds__(256) void txpose_inv()
{
    __shared__ float t[32][33];
    int p0 = blockIdx.x * 32, c0 = blockIdx.y * 32, n = blockIdx.z;
    int tx = threadIdx.x & 31, ty = threadIdx.x >> 5;
    for (int r = ty; r < 32; r += 8)
        t[r][tx] = g_toT[((size_t)n * TVn + p0 + r) * 128 + c0 + tx];
    __syncthreads();
    for (int r = ty; r < 32; r += 8)
        g_tnc[((size_t)n * 128 + c0 + r) * TVn + p0 + tx] = t[tx][r];
}

__global__ __launch_bounds__(256) void txpose_tmaj()
{
    __shared__ float t[32][33];
    int bt = blockIdx.x;
    int t0 = (bt & 3) * 32, c0 = (bt >> 2) * 32;
    int v = blockIdx.y, n = blockIdx.z;
    int tx = threadIdx.x & 31, ty = threadIdx.x >> 5;
    for (int r = ty; r < 32; r += 8)
        t[r][tx] = g_soT[(size_t)n * TVn * 128 + (size_t)((t0 + r) * 25 + v) * 128 + c0 + tx];
    __syncthreads();
    for (int r = ty; r < 32; r += 8)
        g_tmaj[((size_t)(n * 25 + v) * 128 + c0 + r) * 128 + t0 + tx] = t[tx][r];
}

__global__ __launch_bounds__(256)
void satt_kernel(const float* __restrict__ att0, const float* __restrict__ alphas)
{
    int t = blockIdx.x, s = blockIdx.y, n = blockIdx.z;
    __shared__ float qs[32][26], ks[32][26];
    int tid = threadIdx.x;
    const float* qb = g_qkT + (size_t)n * TVn * 192;
    for (int i = tid; i < 832; i += 256) {
        int row = i >> 5, c = i & 31;
        float qv = 0.f, kv = 0.f;
        if (row < 25) {
            qv = qb[(size_t)(t * 25 + row) * 192 + s * 32 + c];
            kv = qb[(size_t)(t * 25 + row) * 192 + 96 + s * 32 + c];
        }
        qs[c][row] = qv;
        ks[c][row] = kv;
    }
    __syncthreads();
    float alpha = alphas[s];
    float* ob = g_atts + (((size_t)(n * 3 + s)) * 128 + t) * 704;
    if (tid < 169) {
        int ti = tid / 13, tj = tid % 13;
        int u0 = ti * 2, v0 = tj * 2;
        float s00 = 0.f, s01 = 0.f, s10 = 0.f, s11 = 0.f;
        #pragma unroll
        for (int c = 0; c < 32; c++) {
            float2 q2 = *(const float2*)&qs[c][u0];
            float2 k2 = *(const float2*)&ks[c][v0];
            s00 += q2.x * k2.x; s01 += q2.x * k2.y;
            s10 += q2.y * k2.x; s11 += q2.y * k2.y;
        }
        float b00 = att0[s * 625 + u0 * 25 + v0];
        float b01 = (v0 + 1 < 25) ? att0[s * 625 + u0 * 25 + v0 + 1] : 0.f;
        float2 o0, o1;
        o0.x = b00 + tanh_ap(s00 * (1.f / 32.f)) * alpha;
        o0.y = (v0 + 1 < 25) ? b01 + tanh_ap(s01 * (1.f / 32.f)) * alpha : 0.f;
        *(float2*)&ob[u0 * 28 + v0] = o0;
        if (u0 + 1 < 25) {
            float b10 = att0[s * 625 + (u0 + 1) * 25 + v0];
            float b11 = (v0 + 1 < 25) ? att0[s * 625 + (u0 + 1) * 25 + v0 + 1] : 0.f;
            o1.x = b10 + tanh_ap(s10 * (1.f / 32.f)) * alpha;
            o1.y = (v0 + 1 < 25) ? b11 + tanh_ap(s11 * (1.f / 32.f)) * alpha : 0.f;
            *(float2*)&ob[(u0 + 1) * 28 + v0] = o1;
        }
    } else if (tid >= 169 && tid < 194) {
        int u = tid - 169;
        *(float2*)&ob[u * 28 + 26] = make_float2(0.f, 0.f);
    }
}

__global__ __launch_bounds__(128)
void ymix_kernel()
{
    int t = blockIdx.x, s = blockIdx.y, n = blockIdx.z;
    __shared__ float4 a4[25][7];
    int c = threadIdx.x;
    const float4* ab4 = (const float4*)(g_atts + (((size_t)(n * 3 + s)) * 128 + t) * 704);
    for (int i = c; i < 175; i += 128) a4[i / 7][i % 7] = ab4[i];
    __syncthreads();
    float xr[25];
    const float* xb = g_xT + (size_t)n * TVn * 128 + (size_t)(t * 25) * 128 + c;
    #pragma unroll
    for (int u = 0; u < 25; u++) xr[u] = xb[u * 128];
    float4 acc[7];
    #pragma unroll
    for (int g = 0; g < 7; g++) acc[g] = make_float4(0.f, 0.f, 0.f, 0.f);
    #pragma unroll
    for (int u = 0; u < 25; u++) {
        float xu = xr[u];
        #pragma unroll
        for (int g = 0; g < 7; g++) {
            float4 av = a4[u][g];
            acc[g].x += xu * av.x; acc[g].y += xu * av.y;
            acc[g].z += xu * av.z; acc[g].w += xu * av.w;
        }
    }
    float* yb = g_yT + (size_t)n * TVn * 384 + (size_t)(t * 25) * 384 + s * 128 + c;
    #pragma unroll
    for (int g = 0; g < 7; g++) {
        const float* ap = (const float*)&acc[g];
        #pragma unroll
        for (int j = 0; j < 4; j++) {
            int v = g * 4 + j;
            if (v < 25) yb[(size_t)v * 384] = ap[j];
        }
    }
}

__global__ void meanv_kernel()
{
    int i = blockIdx.x * blockDim.x + threadIdx.x;
    if (i >= NB * 128 * 128) return;
    int c = i & 127, t = (i >> 7) & 127, n = i >> 14;
    const float* b = g_soT + (size_t)n * TVn * 128 + (size_t)(t * 25) * 128 + c;
    float sum = 0.f;
    #pragma unroll
    for (int v = 0; v < 25; v++) sum += b[v * 128];
    g_sbar[(size_t)n * 16384 + t * 128 + c] = sum * (1.f / 25.f);
}

__global__ __launch_bounds__(256)
void tatt_kernel(const float* __restrict__ af, const float* __restrict__ ab)
{
    int bz = blockIdx.x;
    int n = bz >> 4, s = (bz >> 2) & 3, ug = bz & 3;
    __shared__ float qs[32][129], ksu[32][32];
    int tid = threadIdx.x;
    const float* base = g_qtm + (size_t)n * 32768;
    for (int i = tid; i < 4096; i += 256) {
        int t = i >> 5, c = i & 31;
        qs[c][t] = base[t * 256 + s * 32 + c];
    }
    for (int i = tid; i < 1024; i += 256) {
        int ul = i >> 5, c = i & 31;
        ksu[c][ul] = base[(ug * 32 + ul) * 256 + 128 + s * 32 + c];
    }
    __syncthreads();
    float alpha = (s < 2) ? af[s] : ab[s - 2];
    float* ob = g_att + ((size_t)(n * 4 + s)) * 16384;
    for (int idx = tid; idx < 4096; idx += 256) {
        int ul = idx >> 7, t = idx & 127;
        int u = ug * 32 + ul;
        float sum = 0.f;
        #pragma unroll
        for (int c = 0; c < 32; c++) sum += qs[c][t] * ksu[c][ul];
        float v = tanh_ap(sum * (1.f / 32.f)) * alpha;
        bool keep = (s < 2) ? (t >= u) : (u >= t);
        ob[u * 128 + t] = keep ? v : 0.f;
    }
}

// ---------------- host launcher ----------------
extern "C" void kernel_launch(void* const* d_in, const int* in_sizes, int n_in,
                              void* d_out, int out_size)
{
    const float* x       = (const float*)d_in[0];
    const float* w_in_s  = (const float*)d_in[1];
    const float* b_in_s  = (const float*)d_in[2];
    const float* att0s   = (const float*)d_in[3];
    const float* alphas  = (const float*)d_in[4];
    const float* w_out_s = (const float*)d_in[5];
    const float* b_out_s = (const float*)d_in[6];
    const float* g_out_s = (const float*)d_in[7];
    const float* be_out_s= (const float*)d_in[8];
    const float* w_ff_s  = (const float*)d_in[9];
    const float* b_ff_s  = (const float*)d_in[10];
    const float* g_ff_s  = (const float*)d_in[11];
    const float* be_ff_s = (const float*)d_in[12];
    const float* w_in_t  = (const float*)d_in[13];
    const float* b_in_t  = (const float*)d_in[14];
    const float* al_f    = (const float*)d_in[15];
    const float* al_b    = (const float*)d_in[16];
    const float* w_out_t = (const float*)d_in[17];
    const float* b_out_t = (const float*)d_in[18];
    const float* g_out_t = (const float*)d_in[19];
    const float* be_out_t= (const float*)d_in[20];
    const float* w_ff_t  = (const float*)d_in[21];
    const float* b_ff_t  = (const float*)d_in[22];
    const float* g_ff_t  = (const float*)d_in[23];
    const float* be_ff_t = (const float*)d_in[24];
    const float* w_tcn   = (const float*)d_in[25];
    const float* b_tcn   = (const float*)d_in[26];
    const float* g_tcn   = (const float*)d_in[27];
    const float* be_tcn  = (const float*)d_in[28];
    float* out = (float*)d_out;

    float *wp, *xT, *qkT, *yT, *s1T, *soT, *sbar, *qtm, *att, *tmaj, *zT, *toT, *tnc;
    cudaGetSymbolAddress((void**)&wp,   g_wp);
    cudaGetSymbolAddress((void**)&xT,   g_xT);
    cudaGetSymbolAddress((void**)&qkT,  g_qkT);
    cudaGetSymbolAddress((void**)&yT,   g_yT);
    cudaGetSymbolAddress((void**)&s1T,  g_s1T);
    cudaGetSymbolAddress((void**)&soT,  g_soT);
    cudaGetSymbolAddress((void**)&sbar, g_sbar);
    cudaGetSymbolAddress((void**)&qtm,  g_qtm);
    cudaGetSymbolAddress((void**)&att,  g_att);
    cudaGetSymbolAddress((void**)&tmaj, g_tmaj);
    cudaGetSymbolAddress((void**)&zT,   g_zT);
    cudaGetSymbolAddress((void**)&toT,  g_toT);
    cudaGetSymbolAddress((void**)&tnc,  g_tnc);

    auto G1w = mma_gemm_w<0,0,true,false,false,false,true>;   // qk
    auto G2w = mma_gemm_w<0,0,true,true,true,true,false>;     // bn+res+lrelu
    auto G5w = mma_gemm_w<1,1,true,true,true,true,false>;     // TCN, NCHW out
    auto G3  = mma_gemm<0,0,0,true,false,false,false,false>;  // qtm
    auto G4  = mma_gemm<1,0,2,false,false,false,false,false>; // temporal mix
    cudaFuncSetAttribute(G1w, cudaFuncAttributeMaxDynamicSharedMemorySize, SMEMW);
    cudaFuncSetAttribute(G2w, cudaFuncAttributeMaxDynamicSharedMemorySize, SMEMW);
    cudaFuncSetAttribute(G5w, cudaFuncAttributeMaxDynamicSharedMemorySize, SMEMW);
    cudaFuncSetAttribute(G3,  cudaFuncAttributeMaxDynamicSharedMemorySize, SMEMSZ);
    cudaFuncSetAttribute(G4,  cudaFuncAttributeMaxDynamicSharedMemorySize, SMEMSZ);

    // [0] pack, [1][2] transpose x
    pack_all<<<(W_TOTAL+255)/256,256>>>(w_in_s, w_out_s, w_ff_s, w_in_t, w_out_t, w_ff_t, w_tcn);
    txpose_x<<<dim3(100,4,16),256>>>(x, 0);
    txpose_x<<<dim3(100,4,16),256>>>(x, 16);

    // [3] qk = W_in_s @ x + b  (wide; M padded 256, valid 192)  <- ncu profiles this
    G1w<<<dim3(13,2,NB),512,SMEMW>>>(wp+OFF_WINS, xT, qkT,
        b_in_s, nullptr, nullptr, nullptr, 128, 128, 192, 192, 4, TVn);

    // [4] satt, [5] ymix
    satt_kernel<<<dim3(128,3,NB),256>>>(att0s, alphas);
    ymix_kernel<<<dim3(128,3,NB),128>>>();

    // [6] s1 = lrelu(x + bn(W_out_s @ y + b))  K=384
    G2w<<<dim3(13,1,NB),512,SMEMW>>>(wp+OFF_WOUTS, yT, s1T,
        b_out_s, g_out_s, be_out_s, xT, 384, 384, 128, 128, 12, TVn);

    // [7] sout = lrelu(x + bn(W_ff_s @ s1 + b))
    G2w<<<dim3(13,1,NB),512,SMEMW>>>(wp+OFF_WFFS, s1T, soT,
        b_ff_s, g_ff_s, be_ff_s, xT, 128, 128, 128, 128, 4, TVn);

    // [8] meanv, [9] qtm
    meanv_kernel<<<(NB*128*128+255)/256,256>>>();
    G3<<<dim3(1,2,NB),256,SMEMSZ>>>(wp+OFF_WINT, sbar, qtm,
        b_in_t, nullptr, nullptr, nullptr, 128, 128, 256, 256, 4, 128);

    // [10] tatt
    tatt_kernel<<<NB*16,256>>>(al_f, al_b);

    // [11] sout -> tmaj
    txpose_tmaj<<<dim3(16,25,NB),256>>>();

    // [12] z (temporal mix)
    G4<<<dim3(1,1,NB*100),256,SMEMSZ>>>(att, tmaj, zT,
        nullptr, nullptr, nullptr, nullptr, 128, 128, 512, 128, 4, TVn);

    // [13] t1 = lrelu(sout + bn(W_out_t @ z + b))  K=512
    G2w<<<dim3(13,1,NB),512,SMEMW>>>(wp+OFF_WOUTT, zT, s1T,
        b_out_t, g_out_t, be_out_t, soT, 512, 512, 128, 128, 16, TVn);

    // [14] tout = lrelu(sout + bn(W_ff_t @ t1 + b))
    G2w<<<dim3(13,1,NB),512,SMEMW>>>(wp+OFF_WFFT, s1T, toT,
        b_ff_t, g_ff_t, be_ff_t, soT, 128, 128, 128, 128, 4, TVn);

    // [15] toT -> NCHW
    txpose_inv<<<dim3(100,4,NB),256>>>();

    // [16] out = lrelu(tout + bn(tcn7(tout)+b))  K=896 im2col
    G5w<<<dim3(13,1,NB),512,SMEMW>>>(wp+OFF_WTCN, toT, out,
        b_tcn, g_tcn, be_tcn, tnc, 896, 128, 128, 128, 28, TVn);
}

// round 14
// speedup vs baseline: 1.1994x; 1.0275x over previous
#include <cuda_runtime.h>
#include <cstdint>
#include <math.h>

#define NB 32
#define TVn 3200
#define BN_INV 0.9999950000374997f

// ---------------- scratch ----------------
__device__ float g_wp  [327680];
__device__ float g_xT  [(size_t)NB*TVn*128];
__device__ float g_qkT [(size_t)NB*TVn*192];
__device__ float g_atts[(size_t)NB*3*128*704];
__device__ float g_yT  [(size_t)NB*TVn*384];
__device__ float g_s1T [(size_t)NB*TVn*128];
__device__ float g_soT [(size_t)NB*TVn*128];
__device__ float g_sbar[(size_t)NB*128*128];
__device__ float g_qtm [(size_t)NB*128*256];
__device__ float g_att [(size_t)NB*4*128*128];
__device__ float g_tmaj[(size_t)NB*25*128*128];
__device__ float g_zT  [(size_t)NB*TVn*512];
__device__ float g_toT [(size_t)NB*TVn*128];
__device__ float g_tnc [(size_t)NB*128*TVn];

#define OFF_WINS  0
#define OFF_WOUTS 32768
#define OFF_WFFS  81920
#define OFF_WINT  98304
#define OFF_WOUTT 131072
#define OFF_WFFT  196608
#define OFF_WTCN  212992
#define W_TOTAL   327680

// narrow kernel smem (R11 geometry)
#define RS     36
#define BOFF_F 4608
#define STG_F  9216
#define NSTAGE 3
#define SMEMSZ (STG_F * NSTAGE * 4)     // 110592 B

// wide kernel smem: A 128 rows + B 256 rows, RS stride, 4 stages
#define BOFFW_F 4608
#define STGW_F  13824
#define NSTW    4
#define SMEMW   (STGW_F * NSTW * 4)      // 221184 B

// ---------------- helpers ----------------
__device__ __forceinline__ uint32_t smem_u32(const void* p){
    uint32_t a;
    asm("{ .reg .u64 t; cvta.to.shared.u64 t, %1; cvt.u32.u64 %0, t; }" : "=r"(a) : "l"(p));
    return a;
}
__device__ __forceinline__ uint32_t f2tf32(float f){
    uint32_t r; asm("cvt.rna.tf32.f32 %0, %1;" : "=r"(r) : "f"(f)); return r;
}
__device__ __forceinline__ float tanh_ap(float x){
    float r; asm("tanh.approx.f32 %0, %1;" : "=f"(r) : "f"(x)); return r;
}
__device__ __forceinline__ void mma_tf32(float* d, const uint32_t* a, const uint32_t* b){
    asm volatile("mma.sync.aligned.m16n8k8.row.col.f32.tf32.tf32.f32 "
        "{%0,%1,%2,%3}, {%4,%5,%6,%7}, {%8,%9}, {%0,%1,%2,%3};"
        : "+f"(d[0]), "+f"(d[1]), "+f"(d[2]), "+f"(d[3])
        : "r"(a[0]), "r"(a[1]), "r"(a[2]), "r"(a[3]), "r"(b[0]), "r"(b[1]));
}

// ================= narrow kernel (used by G3 only) =================
__device__ __forceinline__ void compute_chunk(uint32_t stage_b, int lane,
                                              int wm, int wn, float acc[4][4][4]){
    const int arow = (lane & 7) + ((lane >> 3) & 1) * 8;
    const uint32_t aoff = ((lane >> 4) & 1) * 16;
    const int brow = lane & 7;
    const uint32_t boff = ((lane >> 3) & 1) * 16;
    const uint32_t abase = stage_b + (uint32_t)((wm + arow) * RS) * 4u + aoff;
    const uint32_t bbase = stage_b + (uint32_t)(BOFF_F + (wn + brow) * RS) * 4u + boff;
    #pragma unroll
    for (int k8 = 0; k8 < 4; k8++){
        uint32_t af[4][4], bf[4][2];
        #pragma unroll
        for (int mt = 0; mt < 4; mt++){
            uint32_t ad = abase + (uint32_t)(mt * 16 * RS) * 4u + k8 * 32;
            asm volatile("ldmatrix.sync.aligned.m8n8.x4.shared.b16 {%0,%1,%2,%3}, [%4];"
                : "=r"(af[mt][0]), "=r"(af[mt][1]), "=r"(af[mt][2]), "=r"(af[mt][3])
                : "r"(ad));
        }
        #pragma unroll
        for (int nt = 0; nt < 4; nt++){
            uint32_t bd = bbase + (uint32_t)(nt * 8 * RS) * 4u + k8 * 32;
            asm volatile("ldmatrix.sync.aligned.m8n8.x2.shared.b16 {%0,%1}, [%2];"
                : "=r"(bf[nt][0]), "=r"(bf[nt][1])
                : "r"(bd));
        }
        #pragma unroll
        for (int mt = 0; mt < 4; mt++)
            #pragma unroll
            for (int nt = 0; nt < 4; nt++)
                mma_tf32(acc[mt][nt], af[mt], bf[nt]);
    }
}

template<bool BIAS,bool PRED>
__global__ __launch_bounds__(256,2)
void mma_gemm(const float* __restrict__ A, const float* __restrict__ Bp,
              float* __restrict__ Cp, const float* __restrict__ bias,
              int Ka, int Bld, int ldc, int Mvalid, int nch, int Np)
{
    extern __shared__ uint32_t sm[];
    const uint32_t sbw = smem_u32(sm);
    const int tid = threadIdx.x, lane = tid & 31, wid = tid >> 5;
    const int wm = (wid >> 2) * 64, wn = (wid & 3) * 32;
    const int lq = lane >> 2, klo = lane & 3;

    const int n = blockIdx.z;
    const int m0 = blockIdx.y * 128;
    const int p0 = blockIdx.x * 128;
    const float* Bb = Bp + (size_t)n * Np * Bld;

    const int r = tid & 127, kh = (tid >> 7) * 16;
    const float* parow = A + (size_t)(m0 + r) * Ka + kh;

    float acc[4][4][4];
    #pragma unroll
    for (int a = 0; a < 4; a++)
        #pragma unroll
        for (int b = 0; b < 4; b++)
            #pragma unroll
            for (int c = 0; c < 4; c++) acc[a][b][c] = 0.f;

#define ISSUE(cc, stg) {                                                         \
        const int k0_ = (cc) * 32;                                               \
        const float* asrc_ = parow + k0_;                                        \
        const float* bsrc_ = Bb + (size_t)(p0 + r) * Bld + k0_ + kh;             \
        const uint32_t ad_ = sbw + 4u * ((stg) * STG_F + r * RS + kh);           \
        const uint32_t bd_ = sbw + 4u * ((stg) * STG_F + BOFF_F + r * RS + kh);  \
        _Pragma("unroll")                                                        \
        for (int i = 0; i < 4; i++){                                             \
            asm volatile("cp.async.cg.shared.global [%0], [%1], 16;"             \
                         :: "r"(ad_ + 16u*i), "l"(asrc_ + i*4) : "memory");      \
            asm volatile("cp.async.cg.shared.global [%0], [%1], 16;"             \
                         :: "r"(bd_ + 16u*i), "l"(bsrc_ + i*4) : "memory");      \
        } }

    ISSUE(0, 0)
    asm volatile("cp.async.commit_group;" ::: "memory");
    ISSUE(1, 1)
    asm volatile("cp.async.commit_group;" ::: "memory");

    for (int c = 0; c < nch; c++) {
        asm volatile("cp.async.wait_group 1;" ::: "memory");
        __syncthreads();
        compute_chunk(sbw + 4u * ((c % NSTAGE) * STG_F), lane, wm, wn, acc);
        const int nc = c + 2;
        if (nc < nch) { ISSUE(nc, nc % NSTAGE) }
        asm volatile("cp.async.commit_group;" ::: "memory");
    }
#undef ISSUE

    asm volatile("cp.async.wait_group 0;" ::: "memory");
    __syncthreads();
    float* smf = reinterpret_cast<float*>(sm);

    #pragma unroll
    for (int mt = 0; mt < 4; mt++)
        #pragma unroll
        for (int h = 0; h < 2; h++)
            #pragma unroll
            for (int nt = 0; nt < 4; nt++)
                #pragma unroll
                for (int q = 0; q < 2; q++) {
                    const int m = wm + mt*16 + lq + h*8;
                    const int col = wn + nt*8 + klo*2 + q;
                    smf[col*132 + m] = acc[mt][nt][h*2 + q];
                }
    __syncthreads();

    #pragma unroll
    for (int it = 0; it < 16; it++) {
        const int idx = it*256 + tid;
        const int col = idx >> 5, m4 = (idx & 31) * 4;
        const int mg0 = m0 + m4;
        if (PRED && mg0 >= Mvalid) continue;
        float4 v4 = *(float4*)&smf[col*132 + m4];
        float vv[4] = {v4.x, v4.y, v4.z, v4.w};
        float4 b4;
        if (BIAS) b4 = *(const float4*)(bias + mg0);
        const float* bp = (const float*)&b4;
        float4 o4; float* op = (float*)&o4;
        #pragma unroll
        for (int j = 0; j < 4; j++) {
            float v = vv[j];
            if (BIAS) v += bp[j];
            op[j] = v;
        }
        *(float4*)(Cp + ((size_t)n*Np + p0 + col)*ldc + mg0) = o4;
    }
}

// ================= wide kernel: 128M x 256N, 512 threads, 4 stages =================
// ZM 0: A=weights, B per n (Np rows).  ZM 2: temporal mix, bz=(n*4+s), A=att, B=tmaj.
// CM 0: transposed out [p][ldc]; CM 1: NCHW out; CM 3: zT out.
__device__ __forceinline__ void compute_chunk_w(uint32_t stage_b, int lane,
                                                int wm, int wn, float acc[2][8][4]){
    const int arow = (lane & 7) + ((lane >> 3) & 1) * 8;
    const uint32_t aoff = ((lane >> 4) & 1) * 16;
    const int brow = (lane & 7) + ((lane >> 4) & 1) * 8;
    const uint32_t boff = ((lane >> 3) & 1) * 16;
    const uint32_t abase = stage_b + (uint32_t)((wm + arow) * RS) * 4u + aoff;
    const uint32_t bbase = stage_b + (uint32_t)(BOFFW_F + (wn + brow) * RS) * 4u + boff;
    #pragma unroll
    for (int k8 = 0; k8 < 4; k8++){
        uint32_t af[2][4], bf[8][2];
        #pragma unroll
        for (int mt = 0; mt < 2; mt++){
            uint32_t ad = abase + (uint32_t)(mt * 16 * RS) * 4u + k8 * 32;
            asm volatile("ldmatrix.sync.aligned.m8n8.x4.shared.b16 {%0,%1,%2,%3}, [%4];"
                : "=r"(af[mt][0]), "=r"(af[mt][1]), "=r"(af[mt][2]), "=r"(af[mt][3])
                : "r"(ad));
        }
        #pragma unroll
        for (int ng = 0; ng < 4; ng++){
            uint32_t bd = bbase + (uint32_t)(ng * 16 * RS) * 4u + k8 * 32;
            asm volatile("ldmatrix.sync.aligned.m8n8.x4.shared.b16 {%0,%1,%2,%3}, [%4];"
                : "=r"(bf[2*ng][0]), "=r"(bf[2*ng][1]), "=r"(bf[2*ng+1][0]), "=r"(bf[2*ng+1][1])
                : "r"(bd));
        }
        #pragma unroll
        for (int mt = 0; mt < 2; mt++)
            #pragma unroll
            for (int nt = 0; nt < 8; nt++)
                mma_tf32(acc[mt][nt], af[mt], bf[nt]);
    }
}

template<int ZM,int BSHIFT,int CM,bool BIAS,bool BNORM,bool RES,bool LRELU,bool PRED>
__global__ __launch_bounds__(512,1)
void mma_gemm_w(const float* __restrict__ A, const float* __restrict__ Bp,
                float* __restrict__ Cp,
                const float* __restrict__ bias, const float* __restrict__ gam,
                const float* __restrict__ bet, const float* __restrict__ resT,
                int Ka, int Bld, int ldc, int Mvalid, int nch, int Np)
{
    extern __shared__ uint32_t sm[];
    const uint32_t sbw = smem_u32(sm);
    const int tid = threadIdx.x, lane = tid & 31, wid = tid >> 5;
    const int wm = (wid >> 2) * 32, wn = (wid & 3) * 64;
    const int lq = lane >> 2, klo = lane & 3;

    int n, s4 = 0;
    if (ZM == 0) { n = blockIdx.z; }
    else { n = blockIdx.z >> 2; s4 = blockIdx.z & 3; }
    const int m0 = blockIdx.y * 128;
    const int p0 = blockIdx.x * 256;
    const float* Ab = (ZM == 0) ? A : A + (size_t)blockIdx.z * 16384;
    const float* Bb = (ZM == 0) ? Bp + (size_t)n * Np * Bld
                                : Bp + (size_t)n * 25 * 16384;

    float acc[2][8][4];
    #pragma unroll
    for (int a = 0; a < 2; a++)
        #pragma unroll
        for (int b = 0; b < 8; b++)
            #pragma unroll
            for (int c = 0; c < 4; c++) acc[a][b][c] = 0.f;

#define ISSUEW(cc, stg) {                                                        \
        const int k0_ = (cc) * 32;                                               \
        int k0B_, sh_;                                                           \
        if (BSHIFT){ int j_ = (cc) >> 2; k0B_ = ((cc) & 3) * 32; sh_ = (j_-3)*25;}\
        else { k0B_ = k0_; sh_ = 0; }                                            \
        _Pragma("unroll")                                                        \
        for (int i = 0; i < 6; i++){                                             \
            const int slot_ = tid + i * 512;                                     \
            const int row_ = slot_ >> 3, seg_ = slot_ & 7;                       \
            const uint32_t dst_ = sbw + 4u * ((stg) * STGW_F + row_ * RS + seg_ * 4); \
            if (row_ < 128) {                                                    \
                const float* src_ = Ab + (size_t)(m0 + row_) * Ka + k0_ + seg_ * 4; \
                asm volatile("cp.async.cg.shared.global [%0], [%1], 16;"         \
                             :: "r"(dst_), "l"(src_) : "memory");                \
            } else {                                                             \
                const int br_ = row_ - 128;                                      \
                const int gb_ = p0 + br_;                                        \
                const int grow_ = gb_ + sh_;                                     \
                const bool ok_ = ((unsigned)gb_ < (unsigned)Np) &&               \
                                 ((unsigned)grow_ < (unsigned)TVn);              \
                const int bsz_ = ok_ ? 16 : 0;                                   \
                const float* src_ = Bb + (size_t)(ok_ ? grow_ : 0) * Bld + k0B_ + seg_ * 4; \
                asm volatile("cp.async.cg.shared.global [%0], [%1], 16, %2;"     \
                             :: "r"(dst_), "l"(src_), "r"(bsz_) : "memory");     \
            } } }

    ISSUEW(0, 0)
    asm volatile("cp.async.commit_group;" ::: "memory");
    ISSUEW(1, 1)
    asm volatile("cp.async.commit_group;" ::: "memory");
    if (nch > 2) { ISSUEW(2, 2) }
    asm volatile("cp.async.commit_group;" ::: "memory");

    for (int c = 0; c < nch; c++) {
        asm volatile("cp.async.wait_group 2;" ::: "memory");
        __syncthreads();
        compute_chunk_w(sbw + 4u * ((c % NSTW) * STGW_F), lane, wm, wn, acc);
        const int nc = c + 3;
        if (nc < nch) { ISSUEW(nc, nc % NSTW) }
        asm volatile("cp.async.commit_group;" ::: "memory");
    }
#undef ISSUEW

    asm volatile("cp.async.wait_group 0;" ::: "memory");
    float* ep = reinterpret_cast<float*>(sm);

    #pragma unroll
    for (int pass = 0; pass < 4; pass++) {
        __syncthreads();
        if ((wid & 3) == pass) {
            #pragma unroll
            for (int mt = 0; mt < 2; mt++)
                #pragma unroll
                for (int h = 0; h < 2; h++)
                    #pragma unroll
                    for (int nt = 0; nt < 8; nt++)
                        #pragma unroll
                        for (int q = 0; q < 2; q++) {
                            const int m = wm + mt*16 + lq + h*8;
                            const int cl = nt*8 + klo*2 + q;
                            if (CM == 0) ep[cl*132 + m] = acc[mt][nt][h*2 + q];
                            else         ep[m*68 + cl] = acc[mt][nt][h*2 + q];
                        }
        }
        __syncthreads();
        #pragma unroll
        for (int it = 0; it < 4; it++) {
            const int idx = it*512 + tid;
            if (CM == 0) {
                const int cl = idx >> 5, m4 = (idx & 31) * 4;
                const int col = pass*64 + cl;
                const int mg0 = m0 + m4;
                if (PRED && mg0 >= Mvalid) continue;
                if (p0 + col >= Np) continue;
                float4 v4 = *(float4*)&ep[cl*132 + m4];
                float vv[4] = {v4.x, v4.y, v4.z, v4.w};
                float4 b4, g4, e4, r4;
                if (BIAS)  b4 = *(const float4*)(bias + mg0);
                if (BNORM){ g4 = *(const float4*)(gam + mg0); e4 = *(const float4*)(bet + mg0); }
                if (RES)   r4 = *(const float4*)(resT + ((size_t)n*Np + p0 + col)*128 + mg0);
                const float* bp = (const float*)&b4; const float* gp = (const float*)&g4;
                const float* epp = (const float*)&e4; const float* rp = (const float*)&r4;
                float4 o4; float* op = (float*)&o4;
                #pragma unroll
                for (int j = 0; j < 4; j++) {
                    float v = vv[j];
                    if (BIAS)  v += bp[j];
                    if (BNORM) v = v * (gp[j] * BN_INV) + epp[j];
                    if (RES)   v += rp[j];
                    if (LRELU) v = v > 0.f ? v : 0.1f * v;
                    op[j] = v;
                }
                *(float4*)(Cp + ((size_t)n*Np + p0 + col)*ldc + mg0) = o4;
            } else if (CM == 1) {
                const int m = idx >> 4, c4l = (idx & 15) * 4;
                const int col = pass*64 + c4l;
                const int mg = m0 + m;
                if (p0 + col >= Np) continue;
                float4 v4 = *(float4*)&ep[m*68 + c4l];
                float vv[4] = {v4.x, v4.y, v4.z, v4.w};
                float bi = BIAS ? bias[mg] : 0.f;
                float sc = BNORM ? gam[mg] * BN_INV : 1.f;
                float sh = BNORM ? bet[mg] : 0.f;
                float4 r4;
                if (RES) r4 = *(const float4*)(resT + ((size_t)(n*128 + mg))*TVn + p0 + col);
                const float* rp = (const float*)&r4;
                float4 o4; float* op = (float*)&o4;
                #pragma unroll
                for (int j = 0; j < 4; j++) {
                    float v = vv[j] + bi;
                    if (BNORM) v = v * sc + sh;
                    if (RES)   v += rp[j];
                    if (LRELU) v = v > 0.f ? v : 0.1f * v;
                    op[j] = v;
                }
                *(float4*)(Cp + ((size_t)(n*128 + mg))*TVn + p0 + col) = o4;
            } else {
                // CM == 3: zT[n][u*25+v][s4*128+c], gc = p0+pass*64+c4l, v=gc/128, c=gc%128
                const int m = idx >> 4, c4l = (idx & 15) * 4;
                const int gc = p0 + pass*64 + c4l;
                if (gc >= Np) continue;
                const int vv25 = gc >> 7, cmod = gc & 127;
                float4 v4 = *(float4*)&ep[m*68 + (pass*64 + c4l - pass*64)];
                *(float4*)(Cp + ((size_t)n*TVn + (size_t)m*25 + vv25)*512 + s4*128 + cmod) = v4;
            }
        }
    }
}

// ---------------- prep kernels ----------------
__global__ void pack_all(const float* __restrict__ w_in_s, const float* __restrict__ w_out_s,
                         const float* __restrict__ w_ff_s, const float* __restrict__ w_in_t,
                         const float* __restrict__ w_out_t, const float* __restrict__ w_ff_t,
                         const float* __restrict__ w_tcn)
{
    int idx = blockIdx.x * blockDim.x + threadIdx.x;
    if (idx >= W_TOTAL) return;
    const float* src; int off, Msrc, K, tcn = 0;
    if      (idx < OFF_WOUTS){ src = w_in_s;  off = OFF_WINS;  Msrc = 192; K = 128; }
    else if (idx < OFF_WINT) { if (idx < OFF_WFFS){ src = w_out_s; off = OFF_WOUTS; Msrc = 128; K = 384; }
                               else              { src = w_ff_s;  off = OFF_WFFS;  Msrc = 128; K = 128; } }
    else if (idx < OFF_WOUTT){ src = w_in_t;  off = OFF_WINT;  Msrc = 256; K = 128; }
    else if (idx < OFF_WFFT) { src = w_out_t; off = OFF_WOUTT; Msrc = 128; K = 512; }
    else if (idx < OFF_WTCN) { src = w_ff_t;  off = OFF_WFFT;  Msrc = 128; K = 128; }
    else                     { src = w_tcn;   off = OFF_WTCN;  Msrc = 128; K = 896; tcn = 1; }
    int local = idx - off;
    int mrow = local / K, k = local - mrow * K;
    float v = 0.f;
    if (mrow < Msrc) {
        if (tcn) { int j = k >> 7, c = k & 127; v = src[(mrow * 128 + c) * 7 + j]; }
        else     { v = src[(size_t)mrow * K + k]; }
    }
    g_wp[idx] = __uint_as_float(f2tf32(v));
}

__global__ __launch_bounds__(256) void txpose_x(const float* __restrict__ x, int nbase)
{
    __shared__ float t[32][33];
    int p0 = blockIdx.x * 32, c0 = blockIdx.y * 32, n = nbase + blockIdx.z;
    int tx = threadIdx.x & 31, ty = threadIdx.x >> 5;
    for (int r = ty; r < 32; r += 8)
        t[r][tx] = x[((size_t)n * 128 + c0 + r) * TVn + p0 + tx];
    __syncthreads();
    for (int r = ty; r < 32; r += 8)
        g_xT[(size_t)n * TVn * 128 + (size_t)(p0 + r) * 128 + c0 + tx] = t[tx][r];
}

__global__ __launch_bounds__(256) void txpose_inv()
{
    __shared__ float t[32][33];
    int p0 = blockIdx.x * 32, c0 = blockIdx.y * 32, n = blockIdx.z;
    int tx = threadIdx.x & 31, ty = threadIdx.x >> 5;
    for (int r = ty; r < 32; r += 8)
        t[r][tx] = g_toT[((size_t)n * TVn + p0 + r) * 128 + c0 + tx];
    __syncthreads();
    for (int r = ty; r < 32; r += 8)
        g_tnc[((size_t)n * 128 + c0 + r) * TVn + p0 + tx] = t[tx][r];
}

__global__ __launch_bounds__(256) void txpose_tmaj()
{
    __shared__ float t[32][33];
    int bt = blockIdx.x;
    int t0 = (bt & 3) * 32, c0 = (bt >> 2) * 32;
    int v = blockIdx.y, n = blockIdx.z;
    int tx = threadIdx.x & 31, ty = threadIdx.x >> 5;
    for (int r = ty; r < 32; r += 8)
        t[r][tx] = g_soT[(size_t)n * TVn * 128 + (size_t)((t0 + r) * 25 + v) * 128 + c0 + tx];
    __syncthreads();
    for (int r = ty; r < 32; r += 8)
        g_tmaj[((size_t)(n * 25 + v) * 128 + c0 + r) * 128 + t0 + tx] = t[tx][r];
}

__global__ __launch_bounds__(256)
void satt_kernel(const float* __restrict__ att0, const float* __restrict__ alphas)
{
    int t = blockIdx.x, s = blockIdx.y, n = blockIdx.z;
    __shared__ float qs[32][26], ks[32][26];
    int tid = threadIdx.x;
    const float* qb = g_qkT + (size_t)n * TVn * 192;
    for (int i = tid; i < 832; i += 256) {
        int row = i >> 5, c = i & 31;
        float qv = 0.f, kv = 0.f;
        if (row < 25) {
            qv = qb[(size_t)(t * 25 + row) * 192 + s * 32 + c];
            kv = qb[(size_t)(t * 25 + row) * 192 + 96 + s * 32 + c];
        }
        qs[c][row] = qv;
        ks[c][row] = kv;
    }
    __syncthreads();
    float alpha = alphas[s];
    float* ob = g_atts + (((size_t)(n * 3 + s)) * 128 + t) * 704;
    if (tid < 169) {
        int ti = tid / 13, tj = tid % 13;
        int u0 = ti * 2, v0 = tj * 2;
        float s00 = 0.f, s01 = 0.f, s10 = 0.f, s11 = 0.f;
        #pragma unroll
        for (int c = 0; c < 32; c++) {
            float2 q2 = *(const float2*)&qs[c][u0];
            float2 k2 = *(const float2*)&ks[c][v0];
            s00 += q2.x * k2.x; s01 += q2.x * k2.y;
            s10 += q2.y * k2.x; s11 += q2.y * k2.y;
        }
        float b00 = att0[s * 625 + u0 * 25 + v0];
        float b01 = (v0 + 1 < 25) ? att0[s * 625 + u0 * 25 + v0 + 1] : 0.f;
        float2 o0, o1;
        o0.x = b00 + tanh_ap(s00 * (1.f / 32.f)) * alpha;
        o0.y = (v0 + 1 < 25) ? b01 + tanh_ap(s01 * (1.f / 32.f)) * alpha : 0.f;
        *(float2*)&ob[u0 * 28 + v0] = o0;
        if (u0 + 1 < 25) {
            float b10 = att0[s * 625 + (u0 + 1) * 25 + v0];
            float b11 = (v0 + 1 < 25) ? att0[s * 625 + (u0 + 1) * 25 + v0 + 1] : 0.f;
            o1.x = b10 + tanh_ap(s10 * (1.f / 32.f)) * alpha;
            o1.y = (v0 + 1 < 25) ? b11 + tanh_ap(s11 * (1.f / 32.f)) * alpha : 0.f;
            *(float2*)&ob[(u0 + 1) * 28 + v0] = o1;
        }
    } else if (tid >= 169 && tid < 194) {
        int u = tid - 169;
        *(float2*)&ob[u * 28 + 26] = make_float2(0.f, 0.f);
    }
}

__global__ __launch_bounds__(128)
void ymix_kernel()
{
    int t = blockIdx.x, s = blockIdx.y, n = blockIdx.z;
    __shared__ float4 a4[25][7];
    int c = threadIdx.x;
    const float4* ab4 = (const float4*)(g_atts + (((size_t)(n * 3 + s)) * 128 + t) * 704);
    for (int i = c; i < 175; i += 128) a4[i / 7][i % 7] = ab4[i];
    __syncthreads();
    float xr[25];
    const float* xb = g_xT + (size_t)n * TVn * 128 + (size_t)(t * 25) * 128 + c;
    #pragma unroll
    for (int u = 0; u < 25; u++) xr[u] = xb[u * 128];
    float4 acc[7];
    #pragma unroll
    for (int g = 0; g < 7; g++) acc[g] = make_float4(0.f, 0.f, 0.f, 0.f);
    #pragma unroll
    for (int u = 0; u < 25; u++) {
        float xu = xr[u];
        #pragma unroll
        for (int g = 0; g < 7; g++) {
            float4 av = a4[u][g];
            acc[g].x += xu * av.x; acc[g].y += xu * av.y;
            acc[g].z += xu * av.z; acc[g].w += xu * av.w;
        }
    }
    float* yb = g_yT + (size_t)n * TVn * 384 + (size_t)(t * 25) * 384 + s * 128 + c;
    #pragma unroll
    for (int g = 0; g < 7; g++) {
        const float* ap = (const float*)&acc[g];
        #pragma unroll
        for (int j = 0; j < 4; j++) {
            int v = g * 4 + j;
            if (v < 25) yb[(size_t)v * 384] = ap[j];
        }
    }
}

__global__ void meanv_kernel()
{
    int i = blockIdx.x * blockDim.x + threadIdx.x;
    if (i >= NB * 128 * 128) return;
    int c = i & 127, t = (i >> 7) & 127, n = i >> 14;
    const float* b = g_soT + (size_t)n * TVn * 128 + (size_t)(t * 25) * 128 + c;
    float sum = 0.f;
    #pragma unroll
    for (int v = 0; v < 25; v++) sum += b[v * 128];
    g_sbar[(size_t)n * 16384 + t * 128 + c] = sum * (1.f / 25.f);
}

__global__ __launch_bounds__(256)
void tatt_kernel(const float* __restrict__ af, const float* __restrict__ ab)
{
    int bz = blockIdx.x;
    int n = bz >> 4, s = (bz >> 2) & 3, ug = bz & 3;
    __shared__ float qs[32][129], ksu[32][32];
    int tid = threadIdx.x;
    const float* base = g_qtm + (size_t)n * 32768;
    for (int i = tid; i < 4096; i += 256) {
        int t = i >> 5, c = i & 31;
        qs[c][t] = base[t * 256 + s * 32 + c];
    }
    for (int i = tid; i < 1024; i += 256) {
        int ul = i >> 5, c = i & 31;
        ksu[c][ul] = base[(ug * 32 + ul) * 256 + 128 + s * 32 + c];
    }
    __syncthreads();
    float alpha = (s < 2) ? af[s] : ab[s - 2];
    float* ob = g_att + ((size_t)(n * 4 + s)) * 16384;
    for (int idx = tid; idx < 4096; idx += 256) {
        int ul = idx >> 7, t = idx & 127;
        int u = ug * 32 + ul;
        float sum = 0.f;
        #pragma unroll
        for (int c = 0; c < 32; c++) sum += qs[c][t] * ksu[c][ul];
        float v = tanh_ap(sum * (1.f / 32.f)) * alpha;
        bool keep = (s < 2) ? (t >= u) : (u >= t);
        ob[u * 128 + t] = keep ? v : 0.f;
    }
}

// ---------------- host launcher ----------------
extern "C" void kernel_launch(void* const* d_in, const int* in_sizes, int n_in,
                              void* d_out, int out_size)
{
    const float* x       = (const float*)d_in[0];
    const float* w_in_s  = (const float*)d_in[1];
    const float* b_in_s  = (const float*)d_in[2];
    const float* att0s   = (const float*)d_in[3];
    const float* alphas  = (const float*)d_in[4];
    const float* w_out_s = (const float*)d_in[5];
    const float* b_out_s = (const float*)d_in[6];
    const float* g_out_s = (const float*)d_in[7];
    const float* be_out_s= (const float*)d_in[8];
    const float* w_ff_s  = (const float*)d_in[9];
    const float* b_ff_s  = (const float*)d_in[10];
    const float* g_ff_s  = (const float*)d_in[11];
    const float* be_ff_s = (const float*)d_in[12];
    const float* w_in_t  = (const float*)d_in[13];
    const float* b_in_t  = (const float*)d_in[14];
    const float* al_f    = (const float*)d_in[15];
    const float* al_b    = (const float*)d_in[16];
    const float* w_out_t = (const float*)d_in[17];
    const float* b_out_t = (const float*)d_in[18];
    const float* g_out_t = (const float*)d_in[19];
    const float* be_out_t= (const float*)d_in[20];
    const float* w_ff_t  = (const float*)d_in[21];
    const float* b_ff_t  = (const float*)d_in[22];
    const float* g_ff_t  = (const float*)d_in[23];
    const float* be_ff_t = (const float*)d_in[24];
    const float* w_tcn   = (const float*)d_in[25];
    const float* b_tcn   = (const float*)d_in[26];
    const float* g_tcn   = (const float*)d_in[27];
    const float* be_tcn  = (const float*)d_in[28];
    float* out = (float*)d_out;

    float *wp, *xT, *qkT, *yT, *s1T, *soT, *sbar, *qtm, *att, *tmaj, *zT, *toT, *tnc;
    cudaGetSymbolAddress((void**)&wp,   g_wp);
    cudaGetSymbolAddress((void**)&xT,   g_xT);
    cudaGetSymbolAddress((void**)&qkT,  g_qkT);
    cudaGetSymbolAddress((void**)&yT,   g_yT);
    cudaGetSymbolAddress((void**)&s1T,  g_s1T);
    cudaGetSymbolAddress((void**)&soT,  g_soT);
    cudaGetSymbolAddress((void**)&sbar, g_sbar);
    cudaGetSymbolAddress((void**)&qtm,  g_qtm);
    cudaGetSymbolAddress((void**)&att,  g_att);
    cudaGetSymbolAddress((void**)&tmaj, g_tmaj);
    cudaGetSymbolAddress((void**)&zT,   g_zT);
    cudaGetSymbolAddress((void**)&toT,  g_toT);
    cudaGetSymbolAddress((void**)&tnc,  g_tnc);

    auto G1w = mma_gemm_w<0,0,0,true,false,false,false,true>;   // qk
    auto G2w = mma_gemm_w<0,0,0,true,true,true,true,false>;     // bn+res+lrelu
    auto G4w = mma_gemm_w<2,0,3,false,false,false,false,false>; // temporal mix -> zT
    auto G5w = mma_gemm_w<0,1,1,true,true,true,true,false>;     // TCN, NCHW out
    auto G3  = mma_gemm<true,false>;                            // qtm (bias only)
    cudaFuncSetAttribute(G1w, cudaFuncAttributeMaxDynamicSharedMemorySize, SMEMW);
    cudaFuncSetAttribute(G2w, cudaFuncAttributeMaxDynamicSharedMemorySize, SMEMW);
    cudaFuncSetAttribute(G4w, cudaFuncAttributeMaxDynamicSharedMemorySize, SMEMW);
    cudaFuncSetAttribute(G5w, cudaFuncAttributeMaxDynamicSharedMemorySize, SMEMW);
    cudaFuncSetAttribute(G3,  cudaFuncAttributeMaxDynamicSharedMemorySize, SMEMSZ);

    // [0] pack, [1][2] transpose x
    pack_all<<<(W_TOTAL+255)/256,256>>>(w_in_s, w_out_s, w_ff_s, w_in_t, w_out_t, w_ff_t, w_tcn);
    txpose_x<<<dim3(100,4,16),256>>>(x, 0);
    txpose_x<<<dim3(100,4,16),256>>>(x, 16);

    // [3] qk = W_in_s @ x + b  <- ncu profiles this
    G1w<<<dim3(13,2,NB),512,SMEMW>>>(wp+OFF_WINS, xT, qkT,
        b_in_s, nullptr, nullptr, nullptr, 128, 128, 192, 192, 4, TVn);

    // [4] satt, [5] ymix
    satt_kernel<<<dim3(128,3,NB),256>>>(att0s, alphas);
    ymix_kernel<<<dim3(128,3,NB),128>>>();

    // [6] s1 = lrelu(x + bn(W_out_s @ y + b))  K=384
    G2w<<<dim3(13,1,NB),512,SMEMW>>>(wp+OFF_WOUTS, yT, s1T,
        b_out_s, g_out_s, be_out_s, xT, 384, 384, 128, 128, 12, TVn);

    // [7] sout = lrelu(x + bn(W_ff_s @ s1 + b))
    G2w<<<dim3(13,1,NB),512,SMEMW>>>(wp+OFF_WFFS, s1T, soT,
        b_ff_s, g_ff_s, be_ff_s, xT, 128, 128, 128, 128, 4, TVn);

    // [8] meanv, [9] qtm
    meanv_kernel<<<(NB*128*128+255)/256,256>>>();
    G3<<<dim3(1,2,NB),256,SMEMSZ>>>(wp+OFF_WINT, sbar, qtm,
        b_in_t, 128, 128, 256, 256, 4, 128);

    // [10] tatt
    tatt_kernel<<<NB*16,256>>>(al_f, al_b);

    // [11] sout -> tmaj
    txpose_tmaj<<<dim3(16,25,NB),256>>>();

    // [12] z (temporal mix): per (n,s) M=128 N=3200 K=128, wide
    G4w<<<dim3(13,1,NB*4),512,SMEMW>>>(att, tmaj, zT,
        nullptr, nullptr, nullptr, nullptr, 128, 128, 512, 128, 4, TVn);

    // [13] t1 = lrelu(sout + bn(W_out_t @ z + b))  K=512
    G2w<<<dim3(13,1,NB),512,SMEMW>>>(wp+OFF_WOUTT, zT, s1T,
        b_out_t, g_out_t, be_out_t, soT, 512, 512, 128, 128, 16, TVn);

    // [14] tout = lrelu(sout + bn(W_ff_t @ t1 + b))
    G2w<<<dim3(13,1,NB),512,SMEMW>>>(wp+OFF_WFFT, s1T, toT,
        b_ff_t, g_ff_t, be_ff_t, soT, 128, 128, 128, 128, 4, TVn);

    // [15] toT -> NCHW
    txpose_inv<<<dim3(100,4,NB),256>>>();

    // [16] out = lrelu(tout + bn(tcn7(tout)+b))  K=896 im2col
    G5w<<<dim3(13,1,NB),512,SMEMW>>>(wp+OFF_WTCN, toT, out,
        b_tcn, g_tcn, be_tcn, tnc, 896, 128, 128, 128, 28, TVn);
}